// round 2
// baseline (speedup 1.0000x reference)
#include <cuda_runtime.h>
#include <math.h>

#define BB 16
#define NN 512
#define DD 64
#define JT 128
#define BN_EPS 1e-5f

// padded row strides (words). 66: even (8B-aligned pairs), 2-phase conflict-free LDS.64
#define SAS 66
#define SXS 66

// ---------------- scratch (static device globals; no runtime allocation) ----
__device__ float g_agg [BB * NN * DD];   // (B,N,64) attention-aggregated x
__device__ float g_xout[BB * NN * DD];   // pre-batchnorm output
__device__ float g_ps  [512 * 64];       // per-CTA partial sums   (stage 2)
__device__ float g_pq  [512 * 64];       // per-CTA partial sumsq  (stage 2)
__device__ float g_mean[64];
__device__ float g_istd[64];

__device__ __forceinline__ float tanh_fast(float x) {
    float y;
    asm("tanh.approx.f32 %0, %1;" : "=f"(y) : "f"(x));
    return y;
}

// packed f32x2 FMA: acc.lo += a.lo*b.lo ; acc.hi += a.hi*b.hi  (FFMA2 on sm_103a)
#define FFMA2(acc, a, b) \
    asm("fma.rn.f32x2 %0, %1, %2, %0;" : "+l"(acc) : "l"(a), "l"(b))

__device__ __forceinline__ float f32x2_sum(unsigned long long v) {
    float lo, hi;
    asm("mov.b64 {%0, %1}, %2;" : "=f"(lo), "=f"(hi) : "l"(v));
    return lo + hi;
}

// ---------------------------------------------------------------------------
// Stage 1: per (b,i): A = W_att ⊙ x_i ; C = A @ X_b^T ; s_j = Σ_o v_o tanh(C+b);
//          softmax over j ; agg_i = Σ_j a_j x_j
// grid: (NN, BB) blocks, 256 threads. Dynamic smem.
// Inner GEMM uses fma.rn.f32x2 packed over the d (reduction) dimension:
// accumulators carry (even-d, odd-d) partial sums, folded once at the end.
// ---------------------------------------------------------------------------
__global__ void __launch_bounds__(256)
stage1_kernel(const float* __restrict__ x, const float* __restrict__ Wap,
              const float* __restrict__ bap, const float* __restrict__ attw)
{
    extern __shared__ float sm[];
    float* sA   = sm;                 // 64*SAS  scaled weight rows (o-major, padded)
    float* sX   = sA + 64 * SAS;      // 128*SXS j-tile of x_b (padded)
    float* sxi  = sX + 128 * SXS;     // 64
    float* sb   = sxi + 64;           // 64      att bias
    float* sv   = sb + 64;            // 64      att weight vector
    float* ss   = sv + 64;            // 512     scores -> exp weights
    float* sp   = ss + 512;           // 1024    partial buffers
    float* saux = sp + 1024;          // 32      cross-warp reductions

    const int t = threadIdx.x;
    const int lane = t & 31, wid = t >> 5;
    const int b = blockIdx.y, i = blockIdx.x;
    const float* __restrict__ xb = x + (size_t)b * NN * DD;

    if (t < 64) { sxi[t] = xb[i * DD + t]; sb[t] = bap[t]; sv[t] = attw[t]; }
    __syncthreads();
    for (int idx = t; idx < 64 * 64; idx += 256) {
        int o = idx >> 6, d = idx & 63;
        sA[o * SAS + d] = Wap[idx] * sxi[d];
    }
    __syncthreads();

    const int obase = wid * 8;                 // this warp's 8 output rows
    const float* Ar = sA + obase * SAS;

    // ---------------- Pass A: scores for all 512 j ----------------
    for (int jt = 0; jt < 4; ++jt) {
        for (int idx = t; idx < JT * DD; idx += 256) {
            int j = idx >> 6, d = idx & 63;
            sX[j * SXS + d] = xb[(jt * JT + j) * DD + d];
        }
        __syncthreads();

        unsigned long long acc[4][8];
        #pragma unroll
        for (int jj = 0; jj < 4; ++jj)
            #pragma unroll
            for (int oo = 0; oo < 8; ++oo) acc[jj][oo] = 0ULL;

        #pragma unroll 8
        for (int d = 0; d < 64; d += 2) {
            unsigned long long a2[8], x2[4];
            #pragma unroll
            for (int oo = 0; oo < 8; ++oo)      // warp-broadcast 8B loads
                a2[oo] = *reinterpret_cast<const unsigned long long*>(Ar + oo * SAS + d);
            #pragma unroll
            for (int jj = 0; jj < 4; ++jj)
                x2[jj] = *reinterpret_cast<const unsigned long long*>(sX + (lane + 32 * jj) * SXS + d);
            #pragma unroll
            for (int jj = 0; jj < 4; ++jj)
                #pragma unroll
                for (int oo = 0; oo < 8; ++oo)
                    FFMA2(acc[jj][oo], x2[jj], a2[oo]);
        }

        // tanh + weighted partial reduction over this warp's 8 o's
        #pragma unroll
        for (int jj = 0; jj < 4; ++jj) {
            float spart = 0.0f;
            #pragma unroll
            for (int oo = 0; oo < 8; ++oo) {
                float c = f32x2_sum(acc[jj][oo]);
                float h = tanh_fast(c + sb[obase + oo]);
                spart = fmaf(h, sv[obase + oo], spart);
            }
            sp[wid * 128 + lane + 32 * jj] = spart;
        }
        __syncthreads();
        if (t < 128) {
            float s = 0.0f;
            #pragma unroll
            for (int g = 0; g < 8; ++g) s += sp[g * 128 + t];
            ss[jt * JT + t] = s;
        }
        __syncthreads();
    }

    // ---------------- softmax over j (512 values) ----------------
    float mym = fmaxf(ss[t], ss[t + 256]);
    #pragma unroll
    for (int o = 16; o; o >>= 1) mym = fmaxf(mym, __shfl_xor_sync(0xffffffffu, mym, o));
    if (lane == 0) saux[wid] = mym;
    __syncthreads();
    float M = saux[0];
    #pragma unroll
    for (int w = 1; w < 8; ++w) M = fmaxf(M, saux[w]);
    __syncthreads();

    float e0 = __expf(ss[t] - M);
    float e1 = __expf(ss[t + 256] - M);
    ss[t] = e0; ss[t + 256] = e1;
    float sum = e0 + e1;
    #pragma unroll
    for (int o = 16; o; o >>= 1) sum += __shfl_xor_sync(0xffffffffu, sum, o);
    if (lane == 0) saux[wid] = sum;
    __syncthreads();
    float tot = 0.0f;
    #pragma unroll
    for (int w = 0; w < 8; ++w) tot += saux[w];
    const float inv = 1.0f / tot;

    // ---------------- Pass B: agg = (Σ_j e_j x_j) * inv ----------------
    const int d = t & 63, jg = t >> 6;
    float ag = 0.0f;
    for (int jt = 0; jt < 4; ++jt) {
        __syncthreads();
        for (int idx = t; idx < JT * DD; idx += 256) {
            int j = idx >> 6, dd2 = idx & 63;
            sX[j * SXS + dd2] = xb[(jt * JT + j) * DD + dd2];
        }
        __syncthreads();
        const float* as = ss + jt * JT + jg * 32;
        #pragma unroll 8
        for (int jl = 0; jl < 32; ++jl)
            ag = fmaf(as[jl], sX[(jg * 32 + jl) * SXS + d], ag);
    }
    __syncthreads();
    sp[jg * 64 + d] = ag;
    __syncthreads();
    if (t < 64) {
        float a = (sp[t] + sp[64 + t] + sp[128 + t] + sp[192 + t]) * inv;
        g_agg[((size_t)b * NN + i) * DD + t] = a;
    }
}

// ---------------------------------------------------------------------------
// Stage 2: x_out = agg@W_with^T + x@W_without^T + biases ; per-CTA BN partials
// grid: 512 blocks × 256 threads, 16 rows per block.
// ---------------------------------------------------------------------------
__global__ void __launch_bounds__(256)
stage2_kernel(const float* __restrict__ x,
              const float* __restrict__ Wwith, const float* __restrict__ bwith,
              const float* __restrict__ Wwo,   const float* __restrict__ bwo)
{
    __shared__ float sWw[64 * 65], sWo[64 * 65];
    __shared__ float sag[16 * 64], sx[16 * 64];
    __shared__ float rs[4 * 64], rq[4 * 64];

    const int t = threadIdx.x;
    const int r0 = blockIdx.x * 16;

    for (int idx = t; idx < 64 * 64; idx += 256) {
        int o = idx >> 6, d = idx & 63;
        sWw[o * 65 + d] = Wwith[idx];
        sWo[o * 65 + d] = Wwo[idx];
    }
    for (int idx = t; idx < 16 * 64; idx += 256) {
        sag[idx] = g_agg[(size_t)r0 * 64 + idx];
        sx[idx]  = x    [(size_t)r0 * 64 + idx];
    }
    __syncthreads();

    const int o = t & 63, rg = t >> 6;
    const float bias = bwith[o] + bwo[o];
    float lsum = 0.0f, lsq = 0.0f;
    #pragma unroll
    for (int rr = 0; rr < 4; ++rr) {
        const int r = rg + rr * 4;
        float acc = bias;
        #pragma unroll 8
        for (int d = 0; d < 64; ++d)
            acc += sag[r * 64 + d] * sWw[o * 65 + d]
                 + sx [r * 64 + d] * sWo[o * 65 + d];
        g_xout[(size_t)(r0 + r) * 64 + o] = acc;
        lsum += acc;
        lsq  = fmaf(acc, acc, lsq);
    }
    rs[rg * 64 + o] = lsum;
    rq[rg * 64 + o] = lsq;
    __syncthreads();
    if (t < 64) {
        float s = rs[t] + rs[64 + t] + rs[128 + t] + rs[192 + t];
        float q = rq[t] + rq[64 + t] + rq[128 + t] + rq[192 + t];
        g_ps[blockIdx.x * 64 + t] = s;
        g_pq[blockIdx.x * 64 + t] = q;
    }
}

// ---------------------------------------------------------------------------
// Stage 3a: reduce partials -> mean / inv-std (deterministic, no atomics)
// ---------------------------------------------------------------------------
__global__ void stage3a_kernel()
{
    const int o = threadIdx.x;   // 64 threads
    float s = 0.0f, q = 0.0f;
    for (int c = 0; c < 512; ++c) {
        s += g_ps[c * 64 + o];
        q += g_pq[c * 64 + o];
    }
    const float mean = s * (1.0f / 8192.0f);
    const float var  = q * (1.0f / 8192.0f) - mean * mean;
    g_mean[o] = mean;
    g_istd[o] = rsqrtf(var + BN_EPS);
}

// ---------------------------------------------------------------------------
// Stage 3b: batchnorm affine + SELU, write output
// ---------------------------------------------------------------------------
__global__ void __launch_bounds__(512)
stage3b_kernel(const float* __restrict__ gamma, const float* __restrict__ beta,
               float* __restrict__ out)
{
    const int idx = blockIdx.x * 512 + threadIdx.x;
    const int o = idx & 63;
    float v = g_xout[idx];
    float n = (v - g_mean[o]) * g_istd[o] * gamma[o] + beta[o];
    const float alpha = 1.6732632423543772f;
    const float lam   = 1.0507009873554805f;
    out[idx] = (n > 0.0f) ? lam * n : lam * alpha * expm1f(n);
}

// ---------------------------------------------------------------------------
extern "C" void kernel_launch(void* const* d_in, const int* in_sizes, int n_in,
                              void* d_out, int out_size)
{
    const float* x     = (const float*)d_in[0];
    const float* Wap   = (const float*)d_in[1];
    const float* bap   = (const float*)d_in[2];
    const float* attw  = (const float*)d_in[3];
    const float* Wwith = (const float*)d_in[4];
    const float* bwith = (const float*)d_in[5];
    const float* Wwo   = (const float*)d_in[6];
    const float* bwo   = (const float*)d_in[7];
    const float* gamma = (const float*)d_in[8];
    const float* beta  = (const float*)d_in[9];
    float* out = (float*)d_out;

    const int smem1 = (64 * SAS + 128 * SXS + 64 * 3 + 512 + 1024 + 32) * 4; // 57728 B
    cudaFuncSetAttribute(stage1_kernel,
                         cudaFuncAttributeMaxDynamicSharedMemorySize, smem1);

    dim3 g1(NN, BB);
    stage1_kernel<<<g1, 256, smem1>>>(x, Wap, bap, attw);
    stage2_kernel<<<512, 256>>>(x, Wwith, bwith, Wwo, bwo);
    stage3a_kernel<<<1, 64>>>();
    stage3b_kernel<<<(BB * NN * DD) / 512, 512>>>(gamma, beta, out);
}

// round 5
// speedup vs baseline: 3.2560x; 3.2560x over previous
#include <cuda_runtime.h>
#include <cuda_bf16.h>
#include <cstdint>
#include <stdint.h>
#include <math.h>

#define BB 16
#define NN 512
#define DD 64
#define BN_EPS 1e-5f

// ---------------- scratch ---------------------------------------------------
__device__ float g_agg [BB * NN * DD];
__device__ float g_xout[BB * NN * DD];
__device__ float g_ps  [512 * 64];
__device__ float g_pq  [512 * 64];
__device__ float g_mean[64];
__device__ float g_istd[64];

// ---------------- helpers ----------------------------------------------------
__device__ __forceinline__ uint32_t smem_u32(const void* p) {
    uint32_t a;
    asm("{ .reg .u64 t; cvta.to.shared.u64 t, %1; cvt.u32.u64 %0, t; }" : "=r"(a) : "l"(p));
    return a;
}
__device__ __forceinline__ float tanh_fast(float x) {
    float y; asm("tanh.approx.f32 %0, %1;" : "=f"(y) : "f"(x)); return y;
}
__device__ __forceinline__ uint32_t pack_bf16x2(float lo, float hi) {
    __nv_bfloat162 p = __float22bfloat162_rn(make_float2(lo, hi));
    return *reinterpret_cast<uint32_t*>(&p);
}

// m16n8k16 bf16 MMA (legacy HMMA path; valid on base sm_103 target)
__device__ __forceinline__ void mma16816(float& c0, float& c1, float& c2, float& c3,
                                         uint32_t a0, uint32_t a1, uint32_t a2, uint32_t a3,
                                         uint32_t b0, uint32_t b1) {
    asm volatile("mma.sync.aligned.m16n8k16.row.col.f32.bf16.bf16.f32 "
                 "{%0,%1,%2,%3}, {%4,%5,%6,%7}, {%8,%9}, {%0,%1,%2,%3};"
                 : "+f"(c0), "+f"(c1), "+f"(c2), "+f"(c3)
                 : "r"(a0), "r"(a1), "r"(a2), "r"(a3), "r"(b0), "r"(b1));
}
__device__ __forceinline__ void ldmatrix_x4(uint32_t& r0, uint32_t& r1, uint32_t& r2, uint32_t& r3,
                                            uint32_t addr) {
    asm volatile("ldmatrix.sync.aligned.m8n8.x4.shared.b16 {%0,%1,%2,%3}, [%4];"
                 : "=r"(r0), "=r"(r1), "=r"(r2), "=r"(r3) : "r"(addr));
}

// SMEM byte offsets (dynamic)
#define XROW      72                       // bf16 elems per padded X row (144 B)
#define SM_X      0                        // 512 * 144 = 73728
#define SM_W      73728                    // 64*64 fp32 = 16384
#define SM_XI     90112                    // 8*64 fp32  = 2048
#define SM_SSC    92160                    // 8*512 fp32 = 16384
#define SM_SV     108544                   // 64 fp32
#define SM_SB     108800                   // 64 fp32
#define SM_TOTAL  109056

// ---------------------------------------------------------------------------
// Stage 1: CTA = (batch b, 8 i's). Warp w owns i = ibase+w.
// D[j,o] = X[j,:] . (W ⊙ x_i)[o,:] via mma.sync m16n8k16 bf16 (j=M, o=N, d=K).
// B operand built in registers in exact fragment layout.
// Epilogue: s_j = Σ_o v_o tanh(D+b_o) ; warp softmax ; fp32 aggregation.
// grid (64, 16), block 256.
// ---------------------------------------------------------------------------
__global__ void __launch_bounds__(256, 1)
stage1_kernel(const float* __restrict__ x, const float* __restrict__ Wap,
              const float* __restrict__ bap, const float* __restrict__ attw)
{
    extern __shared__ char smem[];
    const uint32_t sb32 = smem_u32(smem);
    const int tid = threadIdx.x, w = tid >> 5, lane = tid & 31;
    const int b = blockIdx.y, ibase = blockIdx.x * 8;
    const float* __restrict__ xb = x + (size_t)b * NN * DD;

    float* sW  = (float*)(smem + SM_W);
    float* sxi = (float*)(smem + SM_XI);
    float* ssc = (float*)(smem + SM_SSC);
    float* sv  = (float*)(smem + SM_SV);
    float* sbi = (float*)(smem + SM_SB);

    // ---- cooperative loads ----
    if (tid < 64) { sv[tid] = attw[tid]; sbi[tid] = bap[tid]; }
    for (int u = tid; u < 64 * 16; u += 256) {           // W fp32 (float4)
        *reinterpret_cast<float4*>(sW + u * 4) = *reinterpret_cast<const float4*>(Wap + u * 4);
    }
    for (int u = tid; u < 8 * 16; u += 256) {            // x_i rows (float4)
        int i = u >> 4, q = u & 15;
        *reinterpret_cast<float4*>(sxi + i * 64 + q * 4) =
            *reinterpret_cast<const float4*>(xb + (ibase + i) * 64 + q * 4);
    }
    for (int u = tid; u < 512 * 16; u += 256) {          // X -> bf16 padded rows
        int r = u >> 4, q = u & 15;
        float4 v4 = *reinterpret_cast<const float4*>(xb + r * 64 + q * 4);
        uint2 pk = make_uint2(pack_bf16x2(v4.x, v4.y), pack_bf16x2(v4.z, v4.w));
        *reinterpret_cast<uint2*>(smem + SM_X + r * (XROW * 2) + q * 8) = pk;
    }
    __syncthreads();

    // ---- build B fragments in registers: B[k=d][n=o] = W[o,d]*xi[d] ----
    // b0: d = kt*16 + (lane&3)*2 + {0,1}; b1: +8,+9 ; o = ot*8 + (lane>>2)
    const float* xi = sxi + w * 64;
    uint32_t Breg[8][4][2];
    #pragma unroll
    for (int ot = 0; ot < 8; ++ot) {
        const int o = ot * 8 + (lane >> 2);
        const float* Wr = sW + o * 64;
        #pragma unroll
        for (int kt = 0; kt < 4; ++kt) {
            const int d0 = kt * 16 + (lane & 3) * 2;
            Breg[ot][kt][0] = pack_bf16x2(Wr[d0]     * xi[d0],     Wr[d0 + 1] * xi[d0 + 1]);
            Breg[ot][kt][1] = pack_bf16x2(Wr[d0 + 8] * xi[d0 + 8], Wr[d0 + 9] * xi[d0 + 9]);
        }
    }
    // preload v,b pairs for this thread's epilogue columns
    float vreg[16], breg[16];
    #pragma unroll
    for (int ot = 0; ot < 8; ++ot) {
        const int o0 = ot * 8 + (lane & 3) * 2;
        vreg[ot * 2]     = sv[o0];     breg[ot * 2]     = sbi[o0];
        vreg[ot * 2 + 1] = sv[o0 + 1]; breg[ot * 2 + 1] = sbi[o0 + 1];
    }

    // ldmatrix address pieces: row = j0 + (lane&15), colelem = kt*16 + (lane>>4)*8
    const int lrow = lane & 15, lcol8 = (lane >> 4) * 8;

    // ---- main loop over 32 j-tiles of 16 ----
    for (int jt = 0; jt < 32; ++jt) {
        const int j0 = jt * 16;
        uint32_t a[4][4];
        #pragma unroll
        for (int kt = 0; kt < 4; ++kt) {
            uint32_t addr = sb32 + SM_X + (j0 + lrow) * (XROW * 2) + (kt * 16 + lcol8) * 2;
            ldmatrix_x4(a[kt][0], a[kt][1], a[kt][2], a[kt][3], addr);
        }
        float c[8][4];
        #pragma unroll
        for (int ot = 0; ot < 8; ++ot) { c[ot][0] = c[ot][1] = c[ot][2] = c[ot][3] = 0.0f; }
        #pragma unroll
        for (int kt = 0; kt < 4; ++kt)
            #pragma unroll
            for (int ot = 0; ot < 8; ++ot)
                mma16816(c[ot][0], c[ot][1], c[ot][2], c[ot][3],
                         a[kt][0], a[kt][1], a[kt][2], a[kt][3],
                         Breg[ot][kt][0], Breg[ot][kt][1]);

        // epilogue: rows r0 = j0+(lane>>2), r1 = r0+8 ; cols o = ot*8+(lane&3)*2+{0,1}
        float s0 = 0.0f, s1 = 0.0f;
        #pragma unroll
        for (int ot = 0; ot < 8; ++ot) {
            s0 = fmaf(vreg[ot*2],   tanh_fast(c[ot][0] + breg[ot*2]),   s0);
            s0 = fmaf(vreg[ot*2+1], tanh_fast(c[ot][1] + breg[ot*2+1]), s0);
            s1 = fmaf(vreg[ot*2],   tanh_fast(c[ot][2] + breg[ot*2]),   s1);
            s1 = fmaf(vreg[ot*2+1], tanh_fast(c[ot][3] + breg[ot*2+1]), s1);
        }
        s0 += __shfl_xor_sync(0xffffffffu, s0, 1);
        s0 += __shfl_xor_sync(0xffffffffu, s0, 2);
        s1 += __shfl_xor_sync(0xffffffffu, s1, 1);
        s1 += __shfl_xor_sync(0xffffffffu, s1, 2);
        if ((lane & 3) == 0) {
            ssc[w * 512 + j0 + (lane >> 2)]     = s0;
            ssc[w * 512 + j0 + (lane >> 2) + 8] = s1;
        }
    }
    __syncwarp();

    // ---- softmax over j (warp-private row) ----
    float* myrow = ssc + w * 512;
    float m = -1e30f;
    for (int j = lane; j < 512; j += 32) m = fmaxf(m, myrow[j]);
    #pragma unroll
    for (int o = 16; o; o >>= 1) m = fmaxf(m, __shfl_xor_sync(0xffffffffu, m, o));
    float sum = 0.0f;
    for (int j = lane; j < 512; j += 32) {
        float e = __expf(myrow[j] - m);
        myrow[j] = e;
        sum += e;
    }
    #pragma unroll
    for (int o = 16; o; o >>= 1) sum += __shfl_xor_sync(0xffffffffu, sum, o);
    const float inv = 1.0f / sum;
    __syncwarp();

    // ---- aggregation: agg = inv * Σ_j e_j x_j (fp32 x from gmem, L1-resident) ----
    {
        float ax = 0.0f, ay = 0.0f;
        const float* xj = xb + lane * 2;
        #pragma unroll 4
        for (int j = 0; j < 512; ++j) {
            float aw = myrow[j];
            float2 xv = *reinterpret_cast<const float2*>(xj + j * 64);
            ax = fmaf(aw, xv.x, ax);
            ay = fmaf(aw, xv.y, ay);
        }
        const int i = ibase + w;
        *reinterpret_cast<float2*>(g_agg + ((size_t)(b * 512 + i)) * 64 + lane * 2) =
            make_float2(ax * inv, ay * inv);
    }
}

// ---------------------------------------------------------------------------
// Stage 2: x_out = agg@W_with^T + x@W_without^T + biases ; per-CTA BN partials
// ---------------------------------------------------------------------------
__global__ void __launch_bounds__(256)
stage2_kernel(const float* __restrict__ x,
              const float* __restrict__ Wwith, const float* __restrict__ bwith,
              const float* __restrict__ Wwo,   const float* __restrict__ bwo)
{
    __shared__ float sWw[64 * 65], sWo[64 * 65];
    __shared__ float sag[16 * 64], sx[16 * 64];
    __shared__ float rs[4 * 64], rq[4 * 64];

    const int t = threadIdx.x;
    const int r0 = blockIdx.x * 16;

    for (int idx = t; idx < 64 * 64; idx += 256) {
        int o = idx >> 6, d = idx & 63;
        sWw[o * 65 + d] = Wwith[idx];
        sWo[o * 65 + d] = Wwo[idx];
    }
    for (int idx = t; idx < 16 * 64; idx += 256) {
        sag[idx] = g_agg[(size_t)r0 * 64 + idx];
        sx[idx]  = x    [(size_t)r0 * 64 + idx];
    }
    __syncthreads();

    const int o = t & 63, rg = t >> 6;
    const float bias = bwith[o] + bwo[o];
    float lsum = 0.0f, lsq = 0.0f;
    #pragma unroll
    for (int rr = 0; rr < 4; ++rr) {
        const int r = rg + rr * 4;
        float acc = bias;
        #pragma unroll 8
        for (int d = 0; d < 64; ++d)
            acc += sag[r * 64 + d] * sWw[o * 65 + d]
                 + sx [r * 64 + d] * sWo[o * 65 + d];
        g_xout[(size_t)(r0 + r) * 64 + o] = acc;
        lsum += acc;
        lsq  = fmaf(acc, acc, lsq);
    }
    rs[rg * 64 + o] = lsum;
    rq[rg * 64 + o] = lsq;
    __syncthreads();
    if (t < 64) {
        float s = rs[t] + rs[64 + t] + rs[128 + t] + rs[192 + t];
        float q = rq[t] + rq[64 + t] + rq[128 + t] + rq[192 + t];
        g_ps[blockIdx.x * 64 + t] = s;
        g_pq[blockIdx.x * 64 + t] = q;
    }
}

__global__ void stage3a_kernel()
{
    const int o = threadIdx.x;
    float s = 0.0f, q = 0.0f;
    for (int c = 0; c < 512; ++c) { s += g_ps[c * 64 + o]; q += g_pq[c * 64 + o]; }
    const float mean = s * (1.0f / 8192.0f);
    const float var  = q * (1.0f / 8192.0f) - mean * mean;
    g_mean[o] = mean;
    g_istd[o] = rsqrtf(var + BN_EPS);
}

__global__ void __launch_bounds__(512)
stage3b_kernel(const float* __restrict__ gamma, const float* __restrict__ beta,
               float* __restrict__ out)
{
    const int idx = blockIdx.x * 512 + threadIdx.x;
    const int o = idx & 63;
    float v = g_xout[idx];
    float n = (v - g_mean[o]) * g_istd[o] * gamma[o] + beta[o];
    const float alpha = 1.6732632423543772f;
    const float lam   = 1.0507009873554805f;
    out[idx] = (n > 0.0f) ? lam * n : lam * alpha * expm1f(n);
}

// ---------------------------------------------------------------------------
extern "C" void kernel_launch(void* const* d_in, const int* in_sizes, int n_in,
                              void* d_out, int out_size)
{
    const float* x     = (const float*)d_in[0];
    const float* Wap   = (const float*)d_in[1];
    const float* bap   = (const float*)d_in[2];
    const float* attw  = (const float*)d_in[3];
    const float* Wwith = (const float*)d_in[4];
    const float* bwith = (const float*)d_in[5];
    const float* Wwo   = (const float*)d_in[6];
    const float* bwo   = (const float*)d_in[7];
    const float* gamma = (const float*)d_in[8];
    const float* beta  = (const float*)d_in[9];
    float* out = (float*)d_out;

    cudaFuncSetAttribute(stage1_kernel,
                         cudaFuncAttributeMaxDynamicSharedMemorySize, SM_TOTAL);

    dim3 g1(64, 16);
    stage1_kernel<<<g1, 256, SM_TOTAL>>>(x, Wap, bap, attw);
    stage2_kernel<<<512, 256>>>(x, Wwith, bwith, Wwo, bwo);
    stage3a_kernel<<<1, 64>>>();
    stage3b_kernel<<<(BB * NN * DD) / 512, 512>>>(gamma, beta, out);
}

// round 7
// speedup vs baseline: 5.7821x; 1.7758x over previous
#include <cuda_runtime.h>
#include <cuda_bf16.h>
#include <cstdint>
#include <stdint.h>
#include <math.h>

#define BB 16
#define NN 512
#define DD 64
#define BN_EPS 1e-5f

// ---------------- scratch ---------------------------------------------------
__device__ float g_scores[BB * NN * NN];   // (B,N,N) raw scores (symmetric)
__device__ float g_agg [BB * NN * DD];
__device__ float g_xout[BB * NN * DD];
__device__ float g_ps  [512 * 64];
__device__ float g_pq  [512 * 64];
__device__ float g_mean[64];
__device__ float g_istd[64];

// ---------------- helpers ----------------------------------------------------
__device__ __forceinline__ uint32_t smem_u32(const void* p) {
    uint32_t a;
    asm("{ .reg .u64 t; cvta.to.shared.u64 t, %1; cvt.u32.u64 %0, t; }" : "=r"(a) : "l"(p));
    return a;
}
__device__ __forceinline__ float tanh_fast(float x) {
    float y; asm("tanh.approx.f32 %0, %1;" : "=f"(y) : "f"(x)); return y;
}
__device__ __forceinline__ uint32_t pack_bf16x2(float lo, float hi) {
    __nv_bfloat162 p = __float22bfloat162_rn(make_float2(lo, hi));
    return *reinterpret_cast<uint32_t*>(&p);
}
__device__ __forceinline__ void mma16816(float& c0, float& c1, float& c2, float& c3,
                                         uint32_t a0, uint32_t a1, uint32_t a2, uint32_t a3,
                                         uint32_t b0, uint32_t b1) {
    asm volatile("mma.sync.aligned.m16n8k16.row.col.f32.bf16.bf16.f32 "
                 "{%0,%1,%2,%3}, {%4,%5,%6,%7}, {%8,%9}, {%0,%1,%2,%3};"
                 : "+f"(c0), "+f"(c1), "+f"(c2), "+f"(c3)
                 : "r"(a0), "r"(a1), "r"(a2), "r"(a3), "r"(b0), "r"(b1));
}
__device__ __forceinline__ void ldmatrix_x4(uint32_t& r0, uint32_t& r1, uint32_t& r2, uint32_t& r3,
                                            uint32_t addr) {
    asm volatile("ldmatrix.sync.aligned.m8n8.x4.shared.b16 {%0,%1,%2,%3}, [%4];"
                 : "=r"(r0), "=r"(r1), "=r"(r2), "=r"(r3) : "r"(addr));
}

// ---------------- score kernel smem layout (bytes) ---------------------------
#define XROW 72                       // bf16 elems per padded row (144 B)
#define SM_XJ   0                     // 64*144 = 9216
#define SM_W    9216                  // 64*65*4 = 16640
#define SM_XI   25856                 // 64*64*4 = 16384
#define SM_SS   42240                 // 64*65*4 = 16640
#define SM_SV   58880                 // 256
#define SM_SB   59136                 // 256
#define SMEM_S  59392

// ---------------------------------------------------------------------------
// Score kernel: CTA = (batch b, upper-tri 64x64 tile pair (ti<=tj)).
// For i in TI, j in TJ: s[i,j] = sum_o v_o tanh( X_j . (W o x_i)[o,:] + b_o )
// MMA m16n8k16 bf16: M=j(16), N=o(8), K=d(16). Warp w handles i = w*8 + 0..7.
// Writes tile AND its transpose to g_scores (symmetry => 56% of full work).
// grid (36, 16), block 256.
// ---------------------------------------------------------------------------
__global__ void __launch_bounds__(256, 1)
score_kernel(const float* __restrict__ x, const float* __restrict__ Wap,
             const float* __restrict__ bap, const float* __restrict__ attw)
{
    extern __shared__ char smem[];
    const uint32_t sb32 = smem_u32(smem);
    const int tid = threadIdx.x, w = tid >> 5, lane = tid & 31;
    const int b = blockIdx.y;

    // decode upper-triangular pair (ti <= tj) from blockIdx.x in [0,36)
    int p = blockIdx.x, ti = 0;
    while (p >= 8 - ti) { p -= 8 - ti; ++ti; }
    const int tj = ti + p;

    const float* __restrict__ xb = x + (size_t)b * NN * DD;

    float* sW  = (float*)(smem + SM_W);    // 64 x 65 fp32 (padded)
    float* sXi = (float*)(smem + SM_XI);   // 64 x 64 fp32 (rows ti*64..)
    float* sS  = (float*)(smem + SM_SS);   // 64 x 65 fp32 s-tile
    float* sv  = (float*)(smem + SM_SV);
    float* sbi = (float*)(smem + SM_SB);

    if (tid < 64) { sv[tid] = attw[tid]; sbi[tid] = bap[tid]; }
    for (int idx = tid; idx < 64 * 64; idx += 256) {         // W padded
        int o = idx >> 6, d = idx & 63;
        sW[o * 65 + d] = Wap[idx];
    }
    for (int u = tid; u < 64 * 16; u += 256) {               // Xi fp32 (float4)
        int r = u >> 4, q = u & 15;
        *reinterpret_cast<float4*>(sXi + r * 64 + q * 4) =
            *reinterpret_cast<const float4*>(xb + (ti * 64 + r) * 64 + q * 4);
    }
    for (int u = tid; u < 64 * 16; u += 256) {               // Xj -> bf16 padded
        int r = u >> 4, q = u & 15;
        float4 v4 = *reinterpret_cast<const float4*>(xb + (tj * 64 + r) * 64 + q * 4);
        uint2 pk = make_uint2(pack_bf16x2(v4.x, v4.y), pack_bf16x2(v4.z, v4.w));
        *reinterpret_cast<uint2*>(smem + SM_XJ + r * (XROW * 2) + q * 8) = pk;
    }
    __syncthreads();

    // epilogue constants per thread
    float vreg[16], breg[16];
    #pragma unroll
    for (int ot = 0; ot < 8; ++ot) {
        const int o0 = ot * 8 + (lane & 3) * 2;
        vreg[ot * 2]     = sv[o0];     breg[ot * 2]     = sbi[o0];
        vreg[ot * 2 + 1] = sv[o0 + 1]; breg[ot * 2 + 1] = sbi[o0 + 1];
    }
    const int lrow = lane & 15, lcol8 = (lane >> 4) * 8;

    for (int il = 0; il < 8; ++il) {
        const int i = w * 8 + il;
        const float* xi = sXi + i * 64;

        // build B fragments: B[k=d][n=o] = W[o,d]*xi[d]
        uint32_t Breg[8][4][2];
        #pragma unroll
        for (int ot = 0; ot < 8; ++ot) {
            const int o = ot * 8 + (lane >> 2);
            const float* Wr = sW + o * 65;
            #pragma unroll
            for (int kt = 0; kt < 4; ++kt) {
                const int d0 = kt * 16 + (lane & 3) * 2;
                Breg[ot][kt][0] = pack_bf16x2(Wr[d0]     * xi[d0],     Wr[d0 + 1] * xi[d0 + 1]);
                Breg[ot][kt][1] = pack_bf16x2(Wr[d0 + 8] * xi[d0 + 8], Wr[d0 + 9] * xi[d0 + 9]);
            }
        }

        #pragma unroll
        for (int jt = 0; jt < 4; ++jt) {
            uint32_t a[4][4];
            #pragma unroll
            for (int kt = 0; kt < 4; ++kt) {
                uint32_t addr = sb32 + SM_XJ + (jt * 16 + lrow) * (XROW * 2) + (kt * 16 + lcol8) * 2;
                ldmatrix_x4(a[kt][0], a[kt][1], a[kt][2], a[kt][3], addr);
            }
            float c[8][4];
            #pragma unroll
            for (int ot = 0; ot < 8; ++ot) { c[ot][0] = c[ot][1] = c[ot][2] = c[ot][3] = 0.0f; }
            #pragma unroll
            for (int kt = 0; kt < 4; ++kt)
                #pragma unroll
                for (int ot = 0; ot < 8; ++ot)
                    mma16816(c[ot][0], c[ot][1], c[ot][2], c[ot][3],
                             a[kt][0], a[kt][1], a[kt][2], a[kt][3],
                             Breg[ot][kt][0], Breg[ot][kt][1]);

            float s0 = 0.0f, s1 = 0.0f;
            #pragma unroll
            for (int ot = 0; ot < 8; ++ot) {
                s0 = fmaf(vreg[ot*2],   tanh_fast(c[ot][0] + breg[ot*2]),   s0);
                s0 = fmaf(vreg[ot*2+1], tanh_fast(c[ot][1] + breg[ot*2+1]), s0);
                s1 = fmaf(vreg[ot*2],   tanh_fast(c[ot][2] + breg[ot*2]),   s1);
                s1 = fmaf(vreg[ot*2+1], tanh_fast(c[ot][3] + breg[ot*2+1]), s1);
            }
            s0 += __shfl_xor_sync(0xffffffffu, s0, 1);
            s0 += __shfl_xor_sync(0xffffffffu, s0, 2);
            s1 += __shfl_xor_sync(0xffffffffu, s1, 1);
            s1 += __shfl_xor_sync(0xffffffffu, s1, 2);
            if ((lane & 3) == 0) {
                sS[i * 65 + jt * 16 + (lane >> 2)]     = s0;
                sS[i * 65 + jt * 16 + 8 + (lane >> 2)] = s1;
            }
        }
    }
    __syncthreads();

    // write normal tile: scores[b][ti*64+i][tj*64+j], coalesced float4
    {
        const int r = tid >> 2, cg = tid & 3;
        float* dst = g_scores + ((size_t)(b * 512 + ti * 64 + r)) * 512 + tj * 64 + cg * 16;
        #pragma unroll
        for (int q = 0; q < 4; ++q) {
            float4 vv = make_float4(sS[r * 65 + cg * 16 + q * 4 + 0],
                                    sS[r * 65 + cg * 16 + q * 4 + 1],
                                    sS[r * 65 + cg * 16 + q * 4 + 2],
                                    sS[r * 65 + cg * 16 + q * 4 + 3]);
            reinterpret_cast<float4*>(dst)[q] = vv;
        }
    }
    // mirror tile (transpose) if off-diagonal
    if (ti != tj) {
        const int jr = tid >> 2, cg = tid & 3;
        float* dst = g_scores + ((size_t)(b * 512 + tj * 64 + jr)) * 512 + ti * 64 + cg * 16;
        #pragma unroll
        for (int q = 0; q < 4; ++q) {
            float4 vv = make_float4(sS[(cg * 16 + q * 4 + 0) * 65 + jr],
                                    sS[(cg * 16 + q * 4 + 1) * 65 + jr],
                                    sS[(cg * 16 + q * 4 + 2) * 65 + jr],
                                    sS[(cg * 16 + q * 4 + 3) * 65 + jr]);
            reinterpret_cast<float4*>(dst)[q] = vv;
        }
    }
}

// ---------------- softmax+agg kernel smem layout -----------------------------
#define EROW 520                      // bf16 elems per padded E row (1040 B)
#define SM_TX   0                     // 512*144 = 73728
#define SM_TE   73728                 // 64*1040 = 66560
#define SM_TINV 140288                // 64 fp32
#define SMEM_T  140544

// ---------------------------------------------------------------------------
// Softmax + aggregation: CTA = (b, 64 i's). Softmax rows from g_scores, E bf16
// in smem; agg[i,d] = (1/S_i) * sum_j E[i,j] X[j,d] via mma (M=i, N=d, K=j).
// grid (8, 16), block 256.
// ---------------------------------------------------------------------------
__global__ void __launch_bounds__(256, 1)
smagg_kernel(const float* __restrict__ x)
{
    extern __shared__ char smem[];
    const uint32_t sb32 = smem_u32(smem);
    const int tid = threadIdx.x, w = tid >> 5, lane = tid & 31;
    const int b = blockIdx.y, ibase = blockIdx.x * 64;
    const float* __restrict__ xb = x + (size_t)b * NN * DD;
    float* sinv = (float*)(smem + SM_TINV);

    // X -> bf16 padded smem
    for (int u = tid; u < 512 * 16; u += 256) {
        int r = u >> 4, q = u & 15;
        float4 v4 = *reinterpret_cast<const float4*>(xb + r * 64 + q * 4);
        uint2 pk = make_uint2(pack_bf16x2(v4.x, v4.y), pack_bf16x2(v4.z, v4.w));
        *reinterpret_cast<uint2*>(smem + SM_TX + r * (XROW * 2) + q * 8) = pk;
    }

    // softmax: warp w handles rows i_loc = w*8 + 0..7
    for (int r = 0; r < 8; ++r) {
        const int il = w * 8 + r;
        const float* srow = g_scores + ((size_t)(b * 512 + ibase + il)) * 512;
        float v[16];
        #pragma unroll
        for (int q = 0; q < 16; ++q) v[q] = srow[lane + q * 32];
        float m = v[0];
        #pragma unroll
        for (int q = 1; q < 16; ++q) m = fmaxf(m, v[q]);
        #pragma unroll
        for (int o = 16; o; o >>= 1) m = fmaxf(m, __shfl_xor_sync(0xffffffffu, m, o));
        float sum = 0.0f;
        #pragma unroll
        for (int q = 0; q < 16; ++q) { v[q] = __expf(v[q] - m); sum += v[q]; }
        #pragma unroll
        for (int o = 16; o; o >>= 1) sum += __shfl_xor_sync(0xffffffffu, sum, o);
        #pragma unroll
        for (int q = 0; q < 16; ++q) {
            *reinterpret_cast<__nv_bfloat16*>(smem + SM_TE + il * (EROW * 2) + (lane + q * 32) * 2) =
                __float2bfloat16(v[q]);
        }
        if (lane == 0) sinv[il] = 1.0f / sum;
    }
    __syncthreads();

    // agg MMA: warp w -> mt = w>>1 (16 i's), ntg = w&1 (4 n8-tiles = 32 d)
    const int mt = w >> 1, ntg = w & 1;
    const int i0 = mt * 16;
    float c[4][4];
    #pragma unroll
    for (int q = 0; q < 4; ++q) { c[q][0] = c[q][1] = c[q][2] = c[q][3] = 0.0f; }

    const int lrow = lane & 15, lcol8 = (lane >> 4) * 8;
    for (int kt = 0; kt < 32; ++kt) {
        const int k0 = kt * 16;
        uint32_t a0, a1, a2, a3;
        {
            uint32_t addr = sb32 + SM_TE + (i0 + lrow) * (EROW * 2) + (k0 + lcol8) * 2;
            ldmatrix_x4(a0, a1, a2, a3, addr);
        }
        const int kb = k0 + (lane & 3) * 2;
        #pragma unroll
        for (int q = 0; q < 4; ++q) {
            const int n = ntg * 32 + q * 8 + (lane >> 2);
            uint32_t lo0 = *reinterpret_cast<const unsigned short*>(smem + SM_TX + (kb)     * (XROW * 2) + n * 2);
            uint32_t hi0 = *reinterpret_cast<const unsigned short*>(smem + SM_TX + (kb + 1) * (XROW * 2) + n * 2);
            uint32_t lo1 = *reinterpret_cast<const unsigned short*>(smem + SM_TX + (kb + 8) * (XROW * 2) + n * 2);
            uint32_t hi1 = *reinterpret_cast<const unsigned short*>(smem + SM_TX + (kb + 9) * (XROW * 2) + n * 2);
            uint32_t b0 = lo0 | (hi0 << 16);
            uint32_t b1 = lo1 | (hi1 << 16);
            mma16816(c[q][0], c[q][1], c[q][2], c[q][3], a0, a1, a2, a3, b0, b1);
        }
    }

    // write agg with normalization
    const int r0 = i0 + (lane >> 2), r1 = r0 + 8;
    const float inv0 = sinv[r0], inv1 = sinv[r1];
    #pragma unroll
    for (int q = 0; q < 4; ++q) {
        const int d0 = ntg * 32 + q * 8 + (lane & 3) * 2;
        *reinterpret_cast<float2*>(g_agg + ((size_t)(b * 512 + ibase + r0)) * 64 + d0) =
            make_float2(c[q][0] * inv0, c[q][1] * inv0);
        *reinterpret_cast<float2*>(g_agg + ((size_t)(b * 512 + ibase + r1)) * 64 + d0) =
            make_float2(c[q][2] * inv1, c[q][3] * inv1);
    }
}

// ---------------------------------------------------------------------------
// Stage 2: x_out = agg@W_with^T + x@W_without^T + biases ; per-CTA BN partials
// ---------------------------------------------------------------------------
__global__ void __launch_bounds__(256)
stage2_kernel(const float* __restrict__ x,
              const float* __restrict__ Wwith, const float* __restrict__ bwith,
              const float* __restrict__ Wwo,   const float* __restrict__ bwo)
{
    __shared__ float sWw[64 * 65], sWo[64 * 65];
    __shared__ float sag[16 * 64], sx[16 * 64];
    __shared__ float rs[4 * 64], rq[4 * 64];

    const int t = threadIdx.x;
    const int r0 = blockIdx.x * 16;

    for (int idx = t; idx < 64 * 64; idx += 256) {
        int o = idx >> 6, d = idx & 63;
        sWw[o * 65 + d] = Wwith[idx];
        sWo[o * 65 + d] = Wwo[idx];
    }
    for (int idx = t; idx < 16 * 64; idx += 256) {
        sag[idx] = g_agg[(size_t)r0 * 64 + idx];
        sx[idx]  = x    [(size_t)r0 * 64 + idx];
    }
    __syncthreads();

    const int o = t & 63, rg = t >> 6;
    const float bias = bwith[o] + bwo[o];
    float lsum = 0.0f, lsq = 0.0f;
    #pragma unroll
    for (int rr = 0; rr < 4; ++rr) {
        const int r = rg + rr * 4;
        float acc = bias;
        #pragma unroll 8
        for (int d = 0; d < 64; ++d)
            acc += sag[r * 64 + d] * sWw[o * 65 + d]
                 + sx [r * 64 + d] * sWo[o * 65 + d];
        g_xout[(size_t)(r0 + r) * 64 + o] = acc;
        lsum += acc;
        lsq  = fmaf(acc, acc, lsq);
    }
    rs[rg * 64 + o] = lsum;
    rq[rg * 64 + o] = lsq;
    __syncthreads();
    if (t < 64) {
        float s = rs[t] + rs[64 + t] + rs[128 + t] + rs[192 + t];
        float q = rq[t] + rq[64 + t] + rq[128 + t] + rq[192 + t];
        g_ps[blockIdx.x * 64 + t] = s;
        g_pq[blockIdx.x * 64 + t] = q;
    }
}

__global__ void stage3a_kernel()
{
    const int o = threadIdx.x;
    float s = 0.0f, q = 0.0f;
    for (int c = 0; c < 512; ++c) { s += g_ps[c * 64 + o]; q += g_pq[c * 64 + o]; }
    const float mean = s * (1.0f / 8192.0f);
    const float var  = q * (1.0f / 8192.0f) - mean * mean;
    g_mean[o] = mean;
    g_istd[o] = rsqrtf(var + BN_EPS);
}

__global__ void __launch_bounds__(512)
stage3b_kernel(const float* __restrict__ gamma, const float* __restrict__ beta,
               float* __restrict__ out)
{
    const int idx = blockIdx.x * 512 + threadIdx.x;
    const int o = idx & 63;
    float v = g_xout[idx];
    float n = (v - g_mean[o]) * g_istd[o] * gamma[o] + beta[o];
    const float alpha = 1.6732632423543772f;
    const float lam   = 1.0507009873554805f;
    out[idx] = (n > 0.0f) ? lam * n : lam * alpha * expm1f(n);
}

// ---------------------------------------------------------------------------
extern "C" void kernel_launch(void* const* d_in, const int* in_sizes, int n_in,
                              void* d_out, int out_size)
{
    const float* x     = (const float*)d_in[0];
    const float* Wap   = (const float*)d_in[1];
    const float* bap   = (const float*)d_in[2];
    const float* attw  = (const float*)d_in[3];
    const float* Wwith = (const float*)d_in[4];
    const float* bwith = (const float*)d_in[5];
    const float* Wwo   = (const float*)d_in[6];
    const float* bwo   = (const float*)d_in[7];
    const float* gamma = (const float*)d_in[8];
    const float* beta  = (const float*)d_in[9];
    float* out = (float*)d_out;

    cudaFuncSetAttribute(score_kernel,
                         cudaFuncAttributeMaxDynamicSharedMemorySize, SMEM_S);
    cudaFuncSetAttribute(smagg_kernel,
                         cudaFuncAttributeMaxDynamicSharedMemorySize, SMEM_T);

    dim3 gs(36, 16);
    score_kernel<<<gs, 256, SMEM_S>>>(x, Wap, bap, attw);
    dim3 gt(8, 16);
    smagg_kernel<<<gt, 256, SMEM_T>>>(x);
    stage2_kernel<<<512, 256>>>(x, Wwith, bwith, Wwo, bwo);
    stage3a_kernel<<<1, 64>>>();
    stage3b_kernel<<<(BB * NN * DD) / 512, 512>>>(gamma, beta, out);
}

// round 9
// speedup vs baseline: 6.2528x; 1.0814x over previous
#include <cuda_runtime.h>
#include <cuda_bf16.h>
#include <cstdint>
#include <stdint.h>
#include <math.h>

#define BB 16
#define NN 512
#define DD 64
#define BN_EPS 1e-5f

// ---------------- scratch ---------------------------------------------------
__device__ float g_scores[BB * NN * NN];   // (B,N,N) raw scores (symmetric)
__device__ float g_agg [BB * NN * DD];
__device__ float g_xout[BB * NN * DD];
__device__ float g_ps  [512 * 64];
__device__ float g_pq  [512 * 64];
__device__ float g_mean[64];
__device__ float g_istd[64];

// ---------------- helpers ----------------------------------------------------
__device__ __forceinline__ uint32_t smem_u32(const void* p) {
    uint32_t a;
    asm("{ .reg .u64 t; cvta.to.shared.u64 t, %1; cvt.u32.u64 %0, t; }" : "=r"(a) : "l"(p));
    return a;
}
__device__ __forceinline__ float tanh_fast(float x) {
    float y; asm("tanh.approx.f32 %0, %1;" : "=f"(y) : "f"(x)); return y;
}
__device__ __forceinline__ uint32_t pack_bf16x2(float lo, float hi) {
    __nv_bfloat162 p = __float22bfloat162_rn(make_float2(lo, hi));
    return *reinterpret_cast<uint32_t*>(&p);
}
__device__ __forceinline__ void mma16816(float& c0, float& c1, float& c2, float& c3,
                                         uint32_t a0, uint32_t a1, uint32_t a2, uint32_t a3,
                                         uint32_t b0, uint32_t b1) {
    asm volatile("mma.sync.aligned.m16n8k16.row.col.f32.bf16.bf16.f32 "
                 "{%0,%1,%2,%3}, {%4,%5,%6,%7}, {%8,%9}, {%0,%1,%2,%3};"
                 : "+f"(c0), "+f"(c1), "+f"(c2), "+f"(c3)
                 : "r"(a0), "r"(a1), "r"(a2), "r"(a3), "r"(b0), "r"(b1));
}
__device__ __forceinline__ void ldmatrix_x4(uint32_t& r0, uint32_t& r1, uint32_t& r2, uint32_t& r3,
                                            uint32_t addr) {
    asm volatile("ldmatrix.sync.aligned.m8n8.x4.shared.b16 {%0,%1,%2,%3}, [%4];"
                 : "=r"(r0), "=r"(r1), "=r"(r2), "=r"(r3) : "r"(addr));
}

// ---------------- score kernel smem layout (bytes) ---------------------------
#define XROW 72                       // bf16 elems per padded row (144 B)
#define SM_XJ   0                     // 64*144 = 9216
#define SM_W    9216                  // 64*65*4 = 16640
#define SM_XI   25856                 // 64*64*4 = 16384
#define SM_SS   42240                 // 64*65*4 = 16640
#define SM_SV   58880                 // 256
#define SM_SB   59136                 // 256
#define SMEM_S  59392

// ---------------------------------------------------------------------------
// Score kernel: CTA = (batch b, upper-tri 64x64 tile pair (ti<=tj)).
// For i in TI, j in TJ: s[i,j] = sum_o v_o tanh( X_j . (W o x_i)[o,:] + b_o )
// MMA m16n8k16 bf16: M=j(16), N=o(8), K=d(16). Warp w handles i = w*8 + 0..7.
// Writes tile AND its transpose to g_scores (symmetry => 56% of full work).
// grid (36, 16), block 256.
// ---------------------------------------------------------------------------
__global__ void __launch_bounds__(256, 1)
score_kernel(const float* __restrict__ x, const float* __restrict__ Wap,
             const float* __restrict__ bap, const float* __restrict__ attw)
{
    extern __shared__ char smem[];
    const uint32_t sb32 = smem_u32(smem);
    const int tid = threadIdx.x, w = tid >> 5, lane = tid & 31;
    const int b = blockIdx.y;

    // decode upper-triangular pair (ti <= tj) from blockIdx.x in [0,36)
    int p = blockIdx.x, ti = 0;
    while (p >= 8 - ti) { p -= 8 - ti; ++ti; }
    const int tj = ti + p;

    const float* __restrict__ xb = x + (size_t)b * NN * DD;

    float* sW  = (float*)(smem + SM_W);    // 64 x 65 fp32 (padded)
    float* sXi = (float*)(smem + SM_XI);   // 64 x 64 fp32 (rows ti*64..)
    float* sS  = (float*)(smem + SM_SS);   // 64 x 65 fp32 s-tile
    float* sv  = (float*)(smem + SM_SV);
    float* sbi = (float*)(smem + SM_SB);

    if (tid < 64) { sv[tid] = attw[tid]; sbi[tid] = bap[tid]; }
    for (int idx = tid; idx < 64 * 64; idx += 256) {         // W padded
        int o = idx >> 6, d = idx & 63;
        sW[o * 65 + d] = Wap[idx];
    }
    for (int u = tid; u < 64 * 16; u += 256) {               // Xi fp32 (float4)
        int r = u >> 4, q = u & 15;
        *reinterpret_cast<float4*>(sXi + r * 64 + q * 4) =
            *reinterpret_cast<const float4*>(xb + (ti * 64 + r) * 64 + q * 4);
    }
    for (int u = tid; u < 64 * 16; u += 256) {               // Xj -> bf16 padded
        int r = u >> 4, q = u & 15;
        float4 v4 = *reinterpret_cast<const float4*>(xb + (tj * 64 + r) * 64 + q * 4);
        uint2 pk = make_uint2(pack_bf16x2(v4.x, v4.y), pack_bf16x2(v4.z, v4.w));
        *reinterpret_cast<uint2*>(smem + SM_XJ + r * (XROW * 2) + q * 8) = pk;
    }
    __syncthreads();

    // epilogue constants per thread
    float vreg[16], breg[16];
    #pragma unroll
    for (int ot = 0; ot < 8; ++ot) {
        const int o0 = ot * 8 + (lane & 3) * 2;
        vreg[ot * 2]     = sv[o0];     breg[ot * 2]     = sbi[o0];
        vreg[ot * 2 + 1] = sv[o0 + 1]; breg[ot * 2 + 1] = sbi[o0 + 1];
    }
    const int lrow = lane & 15, lcol8 = (lane >> 4) * 8;

    for (int il = 0; il < 8; ++il) {
        const int i = w * 8 + il;
        const float* xi = sXi + i * 64;

        // build B fragments: B[k=d][n=o] = W[o,d]*xi[d]
        uint32_t Breg[8][4][2];
        #pragma unroll
        for (int ot = 0; ot < 8; ++ot) {
            const int o = ot * 8 + (lane >> 2);
            const float* Wr = sW + o * 65;
            #pragma unroll
            for (int kt = 0; kt < 4; ++kt) {
                const int d0 = kt * 16 + (lane & 3) * 2;
                Breg[ot][kt][0] = pack_bf16x2(Wr[d0]     * xi[d0],     Wr[d0 + 1] * xi[d0 + 1]);
                Breg[ot][kt][1] = pack_bf16x2(Wr[d0 + 8] * xi[d0 + 8], Wr[d0 + 9] * xi[d0 + 9]);
            }
        }

        #pragma unroll
        for (int jt = 0; jt < 4; ++jt) {
            uint32_t a[4][4];
            #pragma unroll
            for (int kt = 0; kt < 4; ++kt) {
                uint32_t addr = sb32 + SM_XJ + (jt * 16 + lrow) * (XROW * 2) + (kt * 16 + lcol8) * 2;
                ldmatrix_x4(a[kt][0], a[kt][1], a[kt][2], a[kt][3], addr);
            }
            float c[8][4];
            #pragma unroll
            for (int ot = 0; ot < 8; ++ot) { c[ot][0] = c[ot][1] = c[ot][2] = c[ot][3] = 0.0f; }
            #pragma unroll
            for (int kt = 0; kt < 4; ++kt)
                #pragma unroll
                for (int ot = 0; ot < 8; ++ot)
                    mma16816(c[ot][0], c[ot][1], c[ot][2], c[ot][3],
                             a[kt][0], a[kt][1], a[kt][2], a[kt][3],
                             Breg[ot][kt][0], Breg[ot][kt][1]);

            float s0 = 0.0f, s1 = 0.0f;
            #pragma unroll
            for (int ot = 0; ot < 8; ++ot) {
                s0 = fmaf(vreg[ot*2],   tanh_fast(c[ot][0] + breg[ot*2]),   s0);
                s0 = fmaf(vreg[ot*2+1], tanh_fast(c[ot][1] + breg[ot*2+1]), s0);
                s1 = fmaf(vreg[ot*2],   tanh_fast(c[ot][2] + breg[ot*2]),   s1);
                s1 = fmaf(vreg[ot*2+1], tanh_fast(c[ot][3] + breg[ot*2+1]), s1);
            }
            s0 += __shfl_xor_sync(0xffffffffu, s0, 1);
            s0 += __shfl_xor_sync(0xffffffffu, s0, 2);
            s1 += __shfl_xor_sync(0xffffffffu, s1, 1);
            s1 += __shfl_xor_sync(0xffffffffu, s1, 2);
            if ((lane & 3) == 0) {
                sS[i * 65 + jt * 16 + (lane >> 2)]     = s0;
                sS[i * 65 + jt * 16 + 8 + (lane >> 2)] = s1;
            }
        }
    }
    __syncthreads();

    // write normal tile: scores[b][ti*64+i][tj*64+j], coalesced float4
    {
        const int r = tid >> 2, cg = tid & 3;
        float* dst = g_scores + ((size_t)(b * 512 + ti * 64 + r)) * 512 + tj * 64 + cg * 16;
        #pragma unroll
        for (int q = 0; q < 4; ++q) {
            float4 vv = make_float4(sS[r * 65 + cg * 16 + q * 4 + 0],
                                    sS[r * 65 + cg * 16 + q * 4 + 1],
                                    sS[r * 65 + cg * 16 + q * 4 + 2],
                                    sS[r * 65 + cg * 16 + q * 4 + 3]);
            reinterpret_cast<float4*>(dst)[q] = vv;
        }
    }
    // mirror tile (transpose) if off-diagonal
    if (ti != tj) {
        const int jr = tid >> 2, cg = tid & 3;
        float* dst = g_scores + ((size_t)(b * 512 + tj * 64 + jr)) * 512 + ti * 64 + cg * 16;
        #pragma unroll
        for (int q = 0; q < 4; ++q) {
            float4 vv = make_float4(sS[(cg * 16 + q * 4 + 0) * 65 + jr],
                                    sS[(cg * 16 + q * 4 + 1) * 65 + jr],
                                    sS[(cg * 16 + q * 4 + 2) * 65 + jr],
                                    sS[(cg * 16 + q * 4 + 3) * 65 + jr]);
            reinterpret_cast<float4*>(dst)[q] = vv;
        }
    }
}

// ---------------- softmax+agg kernel smem layout -----------------------------
#define EROW 520                      // bf16 elems per padded E row (1040 B)
#define SM_TX   0                     // 512*144 = 73728
#define SM_TE   73728                 // 64*1040 = 66560
#define SM_TINV 140288                // 64 fp32
#define SMEM_T  140544

// ---------------------------------------------------------------------------
// Softmax + aggregation: CTA = (b, 64 i's). Softmax rows from g_scores, E bf16
// in smem; agg[i,d] = (1/S_i) * sum_j E[i,j] X[j,d] via mma (M=i, N=d, K=j).
// grid (8, 16), block 256.
// ---------------------------------------------------------------------------
__global__ void __launch_bounds__(256, 1)
smagg_kernel(const float* __restrict__ x)
{
    extern __shared__ char smem[];
    const uint32_t sb32 = smem_u32(smem);
    const int tid = threadIdx.x, w = tid >> 5, lane = tid & 31;
    const int b = blockIdx.y, ibase = blockIdx.x * 64;
    const float* __restrict__ xb = x + (size_t)b * NN * DD;
    float* sinv = (float*)(smem + SM_TINV);

    // X -> bf16 padded smem
    for (int u = tid; u < 512 * 16; u += 256) {
        int r = u >> 4, q = u & 15;
        float4 v4 = *reinterpret_cast<const float4*>(xb + r * 64 + q * 4);
        uint2 pk = make_uint2(pack_bf16x2(v4.x, v4.y), pack_bf16x2(v4.z, v4.w));
        *reinterpret_cast<uint2*>(smem + SM_TX + r * (XROW * 2) + q * 8) = pk;
    }

    // softmax: warp w handles rows i_loc = w*8 + 0..7
    for (int r = 0; r < 8; ++r) {
        const int il = w * 8 + r;
        const float* srow = g_scores + ((size_t)(b * 512 + ibase + il)) * 512;
        float v[16];
        #pragma unroll
        for (int q = 0; q < 16; ++q) v[q] = srow[lane + q * 32];
        float m = v[0];
        #pragma unroll
        for (int q = 1; q < 16; ++q) m = fmaxf(m, v[q]);
        #pragma unroll
        for (int o = 16; o; o >>= 1) m = fmaxf(m, __shfl_xor_sync(0xffffffffu, m, o));
        float sum = 0.0f;
        #pragma unroll
        for (int q = 0; q < 16; ++q) { v[q] = __expf(v[q] - m); sum += v[q]; }
        #pragma unroll
        for (int o = 16; o; o >>= 1) sum += __shfl_xor_sync(0xffffffffu, sum, o);
        #pragma unroll
        for (int q = 0; q < 16; ++q) {
            *reinterpret_cast<__nv_bfloat16*>(smem + SM_TE + il * (EROW * 2) + (lane + q * 32) * 2) =
                __float2bfloat16(v[q]);
        }
        if (lane == 0) sinv[il] = 1.0f / sum;
    }
    __syncthreads();

    // agg MMA: warp w -> mt = w>>1 (16 i's), ntg = w&1 (4 n8-tiles = 32 d)
    const int mt = w >> 1, ntg = w & 1;
    const int i0 = mt * 16;
    float c[4][4];
    #pragma unroll
    for (int q = 0; q < 4; ++q) { c[q][0] = c[q][1] = c[q][2] = c[q][3] = 0.0f; }

    const int lrow = lane & 15, lcol8 = (lane >> 4) * 8;
    for (int kt = 0; kt < 32; ++kt) {
        const int k0 = kt * 16;
        uint32_t a0, a1, a2, a3;
        {
            uint32_t addr = sb32 + SM_TE + (i0 + lrow) * (EROW * 2) + (k0 + lcol8) * 2;
            ldmatrix_x4(a0, a1, a2, a3, addr);
        }
        const int kb = k0 + (lane & 3) * 2;
        #pragma unroll
        for (int q = 0; q < 4; ++q) {
            const int n = ntg * 32 + q * 8 + (lane >> 2);
            uint32_t lo0 = *reinterpret_cast<const unsigned short*>(smem + SM_TX + (kb)     * (XROW * 2) + n * 2);
            uint32_t hi0 = *reinterpret_cast<const unsigned short*>(smem + SM_TX + (kb + 1) * (XROW * 2) + n * 2);
            uint32_t lo1 = *reinterpret_cast<const unsigned short*>(smem + SM_TX + (kb + 8) * (XROW * 2) + n * 2);
            uint32_t hi1 = *reinterpret_cast<const unsigned short*>(smem + SM_TX + (kb + 9) * (XROW * 2) + n * 2);
            uint32_t b0 = lo0 | (hi0 << 16);
            uint32_t b1 = lo1 | (hi1 << 16);
            mma16816(c[q][0], c[q][1], c[q][2], c[q][3], a0, a1, a2, a3, b0, b1);
        }
    }

    // write agg with normalization
    const int r0 = i0 + (lane >> 2), r1 = r0 + 8;
    const float inv0 = sinv[r0], inv1 = sinv[r1];
    #pragma unroll
    for (int q = 0; q < 4; ++q) {
        const int d0 = ntg * 32 + q * 8 + (lane & 3) * 2;
        *reinterpret_cast<float2*>(g_agg + ((size_t)(b * 512 + ibase + r0)) * 64 + d0) =
            make_float2(c[q][0] * inv0, c[q][1] * inv0);
        *reinterpret_cast<float2*>(g_agg + ((size_t)(b * 512 + ibase + r1)) * 64 + d0) =
            make_float2(c[q][2] * inv1, c[q][3] * inv1);
    }
}

// ---------------------------------------------------------------------------
// Stage 2: x_out = agg@W_with^T + x@W_without^T + biases ; per-CTA BN partials
// ---------------------------------------------------------------------------
__global__ void __launch_bounds__(256)
stage2_kernel(const float* __restrict__ x,
              const float* __restrict__ Wwith, const float* __restrict__ bwith,
              const float* __restrict__ Wwo,   const float* __restrict__ bwo)
{
    __shared__ float sWw[64 * 65], sWo[64 * 65];
    __shared__ float sag[16 * 64], sx[16 * 64];
    __shared__ float rs[4 * 64], rq[4 * 64];

    const int t = threadIdx.x;
    const int r0 = blockIdx.x * 16;

    for (int idx = t; idx < 64 * 64; idx += 256) {
        int o = idx >> 6, d = idx & 63;
        sWw[o * 65 + d] = Wwith[idx];
        sWo[o * 65 + d] = Wwo[idx];
    }
    for (int idx = t; idx < 16 * 64; idx += 256) {
        sag[idx] = g_agg[(size_t)r0 * 64 + idx];
        sx[idx]  = x    [(size_t)r0 * 64 + idx];
    }
    __syncthreads();

    const int o = t & 63, rg = t >> 6;
    const float bias = bwith[o] + bwo[o];
    float lsum = 0.0f, lsq = 0.0f;
    #pragma unroll
    for (int rr = 0; rr < 4; ++rr) {
        const int r = rg + rr * 4;
        float acc = bias;
        #pragma unroll 8
        for (int d = 0; d < 64; ++d)
            acc += sag[r * 64 + d] * sWw[o * 65 + d]
                 + sx [r * 64 + d] * sWo[o * 65 + d];
        g_xout[(size_t)(r0 + r) * 64 + o] = acc;
        lsum += acc;
        lsq  = fmaf(acc, acc, lsq);
    }
    rs[rg * 64 + o] = lsum;
    rq[rg * 64 + o] = lsq;
    __syncthreads();
    if (t < 64) {
        float s = rs[t] + rs[64 + t] + rs[128 + t] + rs[192 + t];
        float q = rq[t] + rq[64 + t] + rq[128 + t] + rq[192 + t];
        g_ps[blockIdx.x * 64 + t] = s;
        g_pq[blockIdx.x * 64 + t] = q;
    }
}

// ---------------------------------------------------------------------------
// Stage 3a: parallel reduce of 512 partials per channel.
// 1 block x 512 threads: channel o = t&63, group g = t>>6 (8 groups of 64).
// ---------------------------------------------------------------------------
__global__ void __launch_bounds__(512)
stage3a_kernel()
{
    __shared__ float rs[512], rq[512];
    const int t = threadIdx.x;
    const int o = t & 63, g = t >> 6;        // 8 groups
    float s = 0.0f, q = 0.0f;
    #pragma unroll 8
    for (int c = g * 64; c < (g + 1) * 64; ++c) {
        s += g_ps[c * 64 + o];
        q += g_pq[c * 64 + o];
    }
    rs[g * 64 + o] = s;
    rq[g * 64 + o] = q;
    __syncthreads();
    if (t < 64) {
        float ss = 0.0f, qq = 0.0f;
        #pragma unroll
        for (int gg = 0; gg < 8; ++gg) { ss += rs[gg * 64 + t]; qq += rq[gg * 64 + t]; }
        const float mean = ss * (1.0f / 8192.0f);
        const float var  = qq * (1.0f / 8192.0f) - mean * mean;
        g_mean[t] = mean;
        g_istd[t] = rsqrtf(var + BN_EPS);
    }
}

__global__ void __launch_bounds__(512)
stage3b_kernel(const float* __restrict__ gamma, const float* __restrict__ beta,
               float* __restrict__ out)
{
    const int idx = blockIdx.x * 512 + threadIdx.x;
    const int o = idx & 63;
    float v = g_xout[idx];
    float n = (v - g_mean[o]) * g_istd[o] * gamma[o] + beta[o];
    const float alpha = 1.6732632423543772f;
    const float lam   = 1.0507009873554805f;
    out[idx] = (n > 0.0f) ? lam * n : lam * alpha * expm1f(n);
}

// ---------------------------------------------------------------------------
extern "C" void kernel_launch(void* const* d_in, const int* in_sizes, int n_in,
                              void* d_out, int out_size)
{
    const float* x     = (const float*)d_in[0];
    const float* Wap   = (const float*)d_in[1];
    const float* bap   = (const float*)d_in[2];
    const float* attw  = (const float*)d_in[3];
    const float* Wwith = (const float*)d_in[4];
    const float* bwith = (const float*)d_in[5];
    const float* Wwo   = (const float*)d_in[6];
    const float* bwo   = (const float*)d_in[7];
    const float* gamma = (const float*)d_in[8];
    const float* beta  = (const float*)d_in[9];
    float* out = (float*)d_out;

    cudaFuncSetAttribute(score_kernel,
                         cudaFuncAttributeMaxDynamicSharedMemorySize, SMEM_S);
    cudaFuncSetAttribute(smagg_kernel,
                         cudaFuncAttributeMaxDynamicSharedMemorySize, SMEM_T);

    dim3 gs(36, 16);
    score_kernel<<<gs, 256, SMEM_S>>>(x, Wap, bap, attw);
    dim3 gt(8, 16);
    smagg_kernel<<<gt, 256, SMEM_T>>>(x);
    stage2_kernel<<<512, 256>>>(x, Wwith, bwith, Wwo, bwo);
    stage3a_kernel<<<1, 512>>>();
    stage3b_kernel<<<(BB * NN * DD) / 512, 512>>>(gamma, beta, out);
}

// round 10
// speedup vs baseline: 6.5904x; 1.0540x over previous
#include <cuda_runtime.h>
#include <cuda_bf16.h>
#include <cstdint>
#include <stdint.h>
#include <math.h>

#define BB 16
#define NN 512
#define DD 64
#define BN_EPS 1e-5f

// ---------------- scratch ---------------------------------------------------
__device__ float g_scores[BB * NN * NN];   // (B,N,N) raw scores (symmetric)
__device__ float g_xout[BB * NN * DD];
__device__ float g_ps  [128 * 64];
__device__ float g_pq  [128 * 64];
__device__ float g_mean[64];
__device__ float g_istd[64];

// ---------------- helpers ----------------------------------------------------
__device__ __forceinline__ uint32_t smem_u32(const void* p) {
    uint32_t a;
    asm("{ .reg .u64 t; cvta.to.shared.u64 t, %1; cvt.u32.u64 %0, t; }" : "=r"(a) : "l"(p));
    return a;
}
__device__ __forceinline__ float tanh_fast(float x) {
    float y; asm("tanh.approx.f32 %0, %1;" : "=f"(y) : "f"(x)); return y;
}
__device__ __forceinline__ uint32_t pack_bf16x2(float lo, float hi) {
    __nv_bfloat162 p = __float22bfloat162_rn(make_float2(lo, hi));
    return *reinterpret_cast<uint32_t*>(&p);
}
__device__ __forceinline__ void mma16816(float& c0, float& c1, float& c2, float& c3,
                                         uint32_t a0, uint32_t a1, uint32_t a2, uint32_t a3,
                                         uint32_t b0, uint32_t b1) {
    asm volatile("mma.sync.aligned.m16n8k16.row.col.f32.bf16.bf16.f32 "
                 "{%0,%1,%2,%3}, {%4,%5,%6,%7}, {%8,%9}, {%0,%1,%2,%3};"
                 : "+f"(c0), "+f"(c1), "+f"(c2), "+f"(c3)
                 : "r"(a0), "r"(a1), "r"(a2), "r"(a3), "r"(b0), "r"(b1));
}
__device__ __forceinline__ void ldmatrix_x4(uint32_t& r0, uint32_t& r1, uint32_t& r2, uint32_t& r3,
                                            uint32_t addr) {
    asm volatile("ldmatrix.sync.aligned.m8n8.x4.shared.b16 {%0,%1,%2,%3}, [%4];"
                 : "=r"(r0), "=r"(r1), "=r"(r2), "=r"(r3) : "r"(addr));
}

// ---------------- score kernel smem layout (bytes) ---------------------------
#define XROW 72                       // bf16 elems per padded row (144 B)
#define SM_XJ   0                     // 64*144 = 9216
#define SM_W    9216                  // 64*65*4 = 16640
#define SM_XI   25856                 // 64*64*4 = 16384
#define SM_SS   42240                 // 64*65*4 = 16640
#define SM_SV   58880                 // 256
#define SM_SB   59136                 // 256
#define SMEM_S  59392

// ---------------------------------------------------------------------------
// Score kernel: CTA = (batch b, upper-tri 64x64 tile pair (ti<=tj)).
// grid (36, 16), block 256.  (unchanged from R7 — at legacy-HMMA rate floor)
// ---------------------------------------------------------------------------
__global__ void __launch_bounds__(256, 1)
score_kernel(const float* __restrict__ x, const float* __restrict__ Wap,
             const float* __restrict__ bap, const float* __restrict__ attw)
{
    extern __shared__ char smem[];
    const uint32_t sb32 = smem_u32(smem);
    const int tid = threadIdx.x, w = tid >> 5, lane = tid & 31;
    const int b = blockIdx.y;

    int p = blockIdx.x, ti = 0;
    while (p >= 8 - ti) { p -= 8 - ti; ++ti; }
    const int tj = ti + p;

    const float* __restrict__ xb = x + (size_t)b * NN * DD;

    float* sW  = (float*)(smem + SM_W);
    float* sXi = (float*)(smem + SM_XI);
    float* sS  = (float*)(smem + SM_SS);
    float* sv  = (float*)(smem + SM_SV);
    float* sbi = (float*)(smem + SM_SB);

    if (tid < 64) { sv[tid] = attw[tid]; sbi[tid] = bap[tid]; }
    for (int idx = tid; idx < 64 * 64; idx += 256) {
        int o = idx >> 6, d = idx & 63;
        sW[o * 65 + d] = Wap[idx];
    }
    for (int u = tid; u < 64 * 16; u += 256) {
        int r = u >> 4, q = u & 15;
        *reinterpret_cast<float4*>(sXi + r * 64 + q * 4) =
            *reinterpret_cast<const float4*>(xb + (ti * 64 + r) * 64 + q * 4);
    }
    for (int u = tid; u < 64 * 16; u += 256) {
        int r = u >> 4, q = u & 15;
        float4 v4 = *reinterpret_cast<const float4*>(xb + (tj * 64 + r) * 64 + q * 4);
        uint2 pk = make_uint2(pack_bf16x2(v4.x, v4.y), pack_bf16x2(v4.z, v4.w));
        *reinterpret_cast<uint2*>(smem + SM_XJ + r * (XROW * 2) + q * 8) = pk;
    }
    __syncthreads();

    float vreg[16], breg[16];
    #pragma unroll
    for (int ot = 0; ot < 8; ++ot) {
        const int o0 = ot * 8 + (lane & 3) * 2;
        vreg[ot * 2]     = sv[o0];     breg[ot * 2]     = sbi[o0];
        vreg[ot * 2 + 1] = sv[o0 + 1]; breg[ot * 2 + 1] = sbi[o0 + 1];
    }
    const int lrow = lane & 15, lcol8 = (lane >> 4) * 8;

    for (int il = 0; il < 8; ++il) {
        const int i = w * 8 + il;
        const float* xi = sXi + i * 64;

        uint32_t Breg[8][4][2];
        #pragma unroll
        for (int ot = 0; ot < 8; ++ot) {
            const int o = ot * 8 + (lane >> 2);
            const float* Wr = sW + o * 65;
            #pragma unroll
            for (int kt = 0; kt < 4; ++kt) {
                const int d0 = kt * 16 + (lane & 3) * 2;
                Breg[ot][kt][0] = pack_bf16x2(Wr[d0]     * xi[d0],     Wr[d0 + 1] * xi[d0 + 1]);
                Breg[ot][kt][1] = pack_bf16x2(Wr[d0 + 8] * xi[d0 + 8], Wr[d0 + 9] * xi[d0 + 9]);
            }
        }

        #pragma unroll
        for (int jt = 0; jt < 4; ++jt) {
            uint32_t a[4][4];
            #pragma unroll
            for (int kt = 0; kt < 4; ++kt) {
                uint32_t addr = sb32 + SM_XJ + (jt * 16 + lrow) * (XROW * 2) + (kt * 16 + lcol8) * 2;
                ldmatrix_x4(a[kt][0], a[kt][1], a[kt][2], a[kt][3], addr);
            }
            float c[8][4];
            #pragma unroll
            for (int ot = 0; ot < 8; ++ot) { c[ot][0] = c[ot][1] = c[ot][2] = c[ot][3] = 0.0f; }
            #pragma unroll
            for (int kt = 0; kt < 4; ++kt)
                #pragma unroll
                for (int ot = 0; ot < 8; ++ot)
                    mma16816(c[ot][0], c[ot][1], c[ot][2], c[ot][3],
                             a[kt][0], a[kt][1], a[kt][2], a[kt][3],
                             Breg[ot][kt][0], Breg[ot][kt][1]);

            float s0 = 0.0f, s1 = 0.0f;
            #pragma unroll
            for (int ot = 0; ot < 8; ++ot) {
                s0 = fmaf(vreg[ot*2],   tanh_fast(c[ot][0] + breg[ot*2]),   s0);
                s0 = fmaf(vreg[ot*2+1], tanh_fast(c[ot][1] + breg[ot*2+1]), s0);
                s1 = fmaf(vreg[ot*2],   tanh_fast(c[ot][2] + breg[ot*2]),   s1);
                s1 = fmaf(vreg[ot*2+1], tanh_fast(c[ot][3] + breg[ot*2+1]), s1);
            }
            s0 += __shfl_xor_sync(0xffffffffu, s0, 1);
            s0 += __shfl_xor_sync(0xffffffffu, s0, 2);
            s1 += __shfl_xor_sync(0xffffffffu, s1, 1);
            s1 += __shfl_xor_sync(0xffffffffu, s1, 2);
            if ((lane & 3) == 0) {
                sS[i * 65 + jt * 16 + (lane >> 2)]     = s0;
                sS[i * 65 + jt * 16 + 8 + (lane >> 2)] = s1;
            }
        }
    }
    __syncthreads();

    {
        const int r = tid >> 2, cg = tid & 3;
        float* dst = g_scores + ((size_t)(b * 512 + ti * 64 + r)) * 512 + tj * 64 + cg * 16;
        #pragma unroll
        for (int q = 0; q < 4; ++q) {
            float4 vv = make_float4(sS[r * 65 + cg * 16 + q * 4 + 0],
                                    sS[r * 65 + cg * 16 + q * 4 + 1],
                                    sS[r * 65 + cg * 16 + q * 4 + 2],
                                    sS[r * 65 + cg * 16 + q * 4 + 3]);
            reinterpret_cast<float4*>(dst)[q] = vv;
        }
    }
    if (ti != tj) {
        const int jr = tid >> 2, cg = tid & 3;
        float* dst = g_scores + ((size_t)(b * 512 + tj * 64 + jr)) * 512 + ti * 64 + cg * 16;
        #pragma unroll
        for (int q = 0; q < 4; ++q) {
            float4 vv = make_float4(sS[(cg * 16 + q * 4 + 0) * 65 + jr],
                                    sS[(cg * 16 + q * 4 + 1) * 65 + jr],
                                    sS[(cg * 16 + q * 4 + 2) * 65 + jr],
                                    sS[(cg * 16 + q * 4 + 3) * 65 + jr]);
            reinterpret_cast<float4*>(dst)[q] = vv;
        }
    }
}

// ---------------- fused softmax+agg+proj kernel smem layout ------------------
#define EROW 520                      // bf16 elems per padded E row (1040 B)
#define SM_TX   0                     // 512*144 = 73728
#define SM_TE   73728                 // 64*1040 = 66560  (reused as sAgg after MMA)
#define SM_TINV 140288                // 256
#define SM_WW   140544                // 64*65*4 = 16640
#define SM_WO   157184                // 16640
#define SM_XF   173824                // 64*64*4 = 16384 (x fp32 rows)
#define SM_RS   190208                // 1024
#define SM_RQ   191232                // 1024
#define SMEM_T  192256

// ---------------------------------------------------------------------------
// Fused: softmax -> agg (MMA) -> x_out projections -> BN partials.
// CTA = (b, 64 i's). grid (8, 16), block 256.
// ---------------------------------------------------------------------------
__global__ void __launch_bounds__(256, 1)
smagg_kernel(const float* __restrict__ x,
             const float* __restrict__ Wwith, const float* __restrict__ bwith,
             const float* __restrict__ Wwo,   const float* __restrict__ bwo)
{
    extern __shared__ char smem[];
    const uint32_t sb32 = smem_u32(smem);
    const int tid = threadIdx.x, w = tid >> 5, lane = tid & 31;
    const int b = blockIdx.y, ibase = blockIdx.x * 64;
    const float* __restrict__ xb = x + (size_t)b * NN * DD;
    float* sinv = (float*)(smem + SM_TINV);
    float* sWw  = (float*)(smem + SM_WW);
    float* sWo  = (float*)(smem + SM_WO);
    float* sXf  = (float*)(smem + SM_XF);
    float* sAgg = (float*)(smem + SM_TE);     // valid after MMA phase
    float* rs   = (float*)(smem + SM_RS);
    float* rq   = (float*)(smem + SM_RQ);

    // ---- early loads: X bf16, weights, x fp32 rows ----
    for (int u = tid; u < 512 * 16; u += 256) {
        int r = u >> 4, q = u & 15;
        float4 v4 = *reinterpret_cast<const float4*>(xb + r * 64 + q * 4);
        uint2 pk = make_uint2(pack_bf16x2(v4.x, v4.y), pack_bf16x2(v4.z, v4.w));
        *reinterpret_cast<uint2*>(smem + SM_TX + r * (XROW * 2) + q * 8) = pk;
    }
    for (int idx = tid; idx < 64 * 64; idx += 256) {
        int o = idx >> 6, d = idx & 63;
        sWw[o * 65 + d] = Wwith[idx];
        sWo[o * 65 + d] = Wwo[idx];
    }
    for (int u = tid; u < 64 * 16; u += 256) {
        int r = u >> 4, q = u & 15;
        *reinterpret_cast<float4*>(sXf + r * 64 + q * 4) =
            *reinterpret_cast<const float4*>(xb + (ibase + r) * 64 + q * 4);
    }

    // ---- softmax: warp w handles rows il = w*8 + 0..7 ----
    for (int r = 0; r < 8; ++r) {
        const int il = w * 8 + r;
        const float* srow = g_scores + ((size_t)(b * 512 + ibase + il)) * 512;
        float v[16];
        #pragma unroll
        for (int q = 0; q < 16; ++q) v[q] = srow[lane + q * 32];
        float m = v[0];
        #pragma unroll
        for (int q = 1; q < 16; ++q) m = fmaxf(m, v[q]);
        #pragma unroll
        for (int o = 16; o; o >>= 1) m = fmaxf(m, __shfl_xor_sync(0xffffffffu, m, o));
        float sum = 0.0f;
        #pragma unroll
        for (int q = 0; q < 16; ++q) { v[q] = __expf(v[q] - m); sum += v[q]; }
        #pragma unroll
        for (int o = 16; o; o >>= 1) sum += __shfl_xor_sync(0xffffffffu, sum, o);
        #pragma unroll
        for (int q = 0; q < 16; ++q) {
            *reinterpret_cast<__nv_bfloat16*>(smem + SM_TE + il * (EROW * 2) + (lane + q * 32) * 2) =
                __float2bfloat16(v[q]);
        }
        if (lane == 0) sinv[il] = 1.0f / sum;
    }
    __syncthreads();

    // ---- agg MMA: warp w -> mt = w>>1 (16 i's), ntg = w&1 (32 d) ----
    const int mt = w >> 1, ntg = w & 1;
    const int i0 = mt * 16;
    float c[4][4];
    #pragma unroll
    for (int q = 0; q < 4; ++q) { c[q][0] = c[q][1] = c[q][2] = c[q][3] = 0.0f; }

    const int lrow = lane & 15, lcol8 = (lane >> 4) * 8;
    for (int kt = 0; kt < 32; ++kt) {
        const int k0 = kt * 16;
        uint32_t a0, a1, a2, a3;
        {
            uint32_t addr = sb32 + SM_TE + (i0 + lrow) * (EROW * 2) + (k0 + lcol8) * 2;
            ldmatrix_x4(a0, a1, a2, a3, addr);
        }
        const int kb = k0 + (lane & 3) * 2;
        #pragma unroll
        for (int q = 0; q < 4; ++q) {
            const int n = ntg * 32 + q * 8 + (lane >> 2);
            uint32_t lo0 = *reinterpret_cast<const unsigned short*>(smem + SM_TX + (kb)     * (XROW * 2) + n * 2);
            uint32_t hi0 = *reinterpret_cast<const unsigned short*>(smem + SM_TX + (kb + 1) * (XROW * 2) + n * 2);
            uint32_t lo1 = *reinterpret_cast<const unsigned short*>(smem + SM_TX + (kb + 8) * (XROW * 2) + n * 2);
            uint32_t hi1 = *reinterpret_cast<const unsigned short*>(smem + SM_TX + (kb + 9) * (XROW * 2) + n * 2);
            uint32_t b0 = lo0 | (hi0 << 16);
            uint32_t b1 = lo1 | (hi1 << 16);
            mma16816(c[q][0], c[q][1], c[q][2], c[q][3], a0, a1, a2, a3, b0, b1);
        }
    }
    __syncthreads();   // E no longer needed; TE region becomes sAgg

    // ---- write normalized agg into smem ----
    {
        const int r0 = i0 + (lane >> 2), r1 = r0 + 8;
        const float inv0 = sinv[r0], inv1 = sinv[r1];
        #pragma unroll
        for (int q = 0; q < 4; ++q) {
            const int d0 = ntg * 32 + q * 8 + (lane & 3) * 2;
            sAgg[r0 * 64 + d0]     = c[q][0] * inv0;
            sAgg[r0 * 64 + d0 + 1] = c[q][1] * inv0;
            sAgg[r1 * 64 + d0]     = c[q][2] * inv1;
            sAgg[r1 * 64 + d0 + 1] = c[q][3] * inv1;
        }
    }
    __syncthreads();

    // ---- projections + BN partials (former stage2, 64 rows) ----
    {
        const int o = tid & 63, rg = tid >> 6;     // 4 groups x 16 rows
        const float bias = bwith[o] + bwo[o];
        float lsum = 0.0f, lsq = 0.0f;
        for (int rr = 0; rr < 16; ++rr) {
            const int r = rg * 16 + rr;
            float acc = bias;
            #pragma unroll 8
            for (int d = 0; d < 64; ++d)
                acc += sAgg[r * 64 + d] * sWw[o * 65 + d]
                     + sXf [r * 64 + d] * sWo[o * 65 + d];
            g_xout[(size_t)(b * 512 + ibase + r) * 64 + o] = acc;
            lsum += acc;
            lsq  = fmaf(acc, acc, lsq);
        }
        rs[rg * 64 + o] = lsum;
        rq[rg * 64 + o] = lsq;
    }
    __syncthreads();
    if (tid < 64) {
        float s = rs[tid] + rs[64 + tid] + rs[128 + tid] + rs[192 + tid];
        float q = rq[tid] + rq[64 + tid] + rq[128 + tid] + rq[192 + tid];
        const int cta = blockIdx.y * 8 + blockIdx.x;   // 0..127
        g_ps[cta * 64 + tid] = s;
        g_pq[cta * 64 + tid] = q;
    }
}

// ---------------------------------------------------------------------------
// Stage 3a: one block per channel; 128 partials each. grid 64 x 128 threads.
// ---------------------------------------------------------------------------
__global__ void __launch_bounds__(128)
stage3a_kernel()
{
    __shared__ float rs[128], rq[128];
    const int o = blockIdx.x, t = threadIdx.x;
    rs[t] = g_ps[t * 64 + o];
    rq[t] = g_pq[t * 64 + o];
    __syncthreads();
    if (t < 32) {
        float ss = rs[t] + rs[t + 32] + rs[t + 64] + rs[t + 96];
        float qq = rq[t] + rq[t + 32] + rq[t + 64] + rq[t + 96];
        #pragma unroll
        for (int off = 16; off; off >>= 1) {
            ss += __shfl_xor_sync(0xffffffffu, ss, off);
            qq += __shfl_xor_sync(0xffffffffu, qq, off);
        }
        if (t == 0) {
            const float mean = ss * (1.0f / 8192.0f);
            const float var  = qq * (1.0f / 8192.0f) - mean * mean;
            g_mean[o] = mean;
            g_istd[o] = rsqrtf(var + BN_EPS);
        }
    }
}

__global__ void __launch_bounds__(512)
stage3b_kernel(const float* __restrict__ gamma, const float* __restrict__ beta,
               float* __restrict__ out)
{
    const int idx = blockIdx.x * 512 + threadIdx.x;
    const int o = idx & 63;
    float v = g_xout[idx];
    float n = (v - g_mean[o]) * g_istd[o] * gamma[o] + beta[o];
    const float alpha = 1.6732632423543772f;
    const float lam   = 1.0507009873554805f;
    out[idx] = (n > 0.0f) ? lam * n : lam * alpha * expm1f(n);
}

// ---------------------------------------------------------------------------
extern "C" void kernel_launch(void* const* d_in, const int* in_sizes, int n_in,
                              void* d_out, int out_size)
{
    const float* x     = (const float*)d_in[0];
    const float* Wap   = (const float*)d_in[1];
    const float* bap   = (const float*)d_in[2];
    const float* attw  = (const float*)d_in[3];
    const float* Wwith = (const float*)d_in[4];
    const float* bwith = (const float*)d_in[5];
    const float* Wwo   = (const float*)d_in[6];
    const float* bwo   = (const float*)d_in[7];
    const float* gamma = (const float*)d_in[8];
    const float* beta  = (const float*)d_in[9];
    float* out = (float*)d_out;

    cudaFuncSetAttribute(score_kernel,
                         cudaFuncAttributeMaxDynamicSharedMemorySize, SMEM_S);
    cudaFuncSetAttribute(smagg_kernel,
                         cudaFuncAttributeMaxDynamicSharedMemorySize, SMEM_T);

    dim3 gs(36, 16);
    score_kernel<<<gs, 256, SMEM_S>>>(x, Wap, bap, attw);
    dim3 gt(8, 16);
    smagg_kernel<<<gt, 256, SMEM_T>>>(x, Wwith, bwith, Wwo, bwo);
    stage3a_kernel<<<64, 128>>>();
    stage3b_kernel<<<(BB * NN * DD) / 512, 512>>>(gamma, beta, out);
}

// round 12
// speedup vs baseline: 7.3930x; 1.1218x over previous
#include <cuda_runtime.h>
#include <cuda_bf16.h>
#include <cstdint>
#include <stdint.h>
#include <math.h>

#define BB 16
#define NN 512
#define DD 64
#define BN_EPS 1e-5f

// ---------------- scratch ---------------------------------------------------
__device__ float g_scores[BB * NN * NN];   // (B,N,N) raw scores (symmetric)
__device__ float g_xout[BB * NN * DD];
__device__ float g_ps  [128 * 64];
__device__ float g_pq  [128 * 64];
__device__ float g_mean[64];
__device__ float g_istd[64];

// ---------------- helpers ----------------------------------------------------
__device__ __forceinline__ uint32_t smem_u32(const void* p) {
    uint32_t a;
    asm("{ .reg .u64 t; cvta.to.shared.u64 t, %1; cvt.u32.u64 %0, t; }" : "=r"(a) : "l"(p));
    return a;
}
__device__ __forceinline__ float tanh_fast(float x) {
    float y; asm("tanh.approx.f32 %0, %1;" : "=f"(y) : "f"(x)); return y;
}
__device__ __forceinline__ uint32_t pack_bf16x2(float lo, float hi) {
    __nv_bfloat162 p = __float22bfloat162_rn(make_float2(lo, hi));
    return *reinterpret_cast<uint32_t*>(&p);
}
__device__ __forceinline__ void mma16816(float& c0, float& c1, float& c2, float& c3,
                                         uint32_t a0, uint32_t a1, uint32_t a2, uint32_t a3,
                                         uint32_t b0, uint32_t b1) {
    asm volatile("mma.sync.aligned.m16n8k16.row.col.f32.bf16.bf16.f32 "
                 "{%0,%1,%2,%3}, {%4,%5,%6,%7}, {%8,%9}, {%0,%1,%2,%3};"
                 : "+f"(c0), "+f"(c1), "+f"(c2), "+f"(c3)
                 : "r"(a0), "r"(a1), "r"(a2), "r"(a3), "r"(b0), "r"(b1));
}
__device__ __forceinline__ void ldmatrix_x4(uint32_t& r0, uint32_t& r1, uint32_t& r2, uint32_t& r3,
                                            uint32_t addr) {
    asm volatile("ldmatrix.sync.aligned.m8n8.x4.shared.b16 {%0,%1,%2,%3}, [%4];"
                 : "=r"(r0), "=r"(r1), "=r"(r2), "=r"(r3) : "r"(addr));
}

// ---------------- score kernel smem layout (bytes) ---------------------------
#define XROW 72                       // bf16 elems per padded row (144 B)
#define SM_XJ   0                     // 64*144 = 9216
#define SM_W    9216                  // 64*65*4 = 16640
#define SM_XI   25856                 // 64*64*4 = 16384
#define SM_SS   42240                 // 64*65*4 = 16640
#define SM_SV   58880                 // 256
#define SM_SB   59136                 // 256
#define SMEM_S  59392

// ---------------------------------------------------------------------------
// Score kernel: CTA = (batch b, upper-tri 64x64 tile pair (ti<=tj)).
// grid (36, 16), block 256, 2 CTAs/SM (o-dim split into two halves to cut
// registers; scores accumulated across halves via smem RMW).
// ---------------------------------------------------------------------------
__global__ void __launch_bounds__(256, 2)
score_kernel(const float* __restrict__ x, const float* __restrict__ Wap,
             const float* __restrict__ bap, const float* __restrict__ attw)
{
    extern __shared__ char smem[];
    const uint32_t sb32 = smem_u32(smem);
    const int tid = threadIdx.x, w = tid >> 5, lane = tid & 31;
    const int b = blockIdx.y;

    int p = blockIdx.x, ti = 0;
    while (p >= 8 - ti) { p -= 8 - ti; ++ti; }
    const int tj = ti + p;

    const float* __restrict__ xb = x + (size_t)b * NN * DD;

    float* sW  = (float*)(smem + SM_W);
    float* sXi = (float*)(smem + SM_XI);
    float* sS  = (float*)(smem + SM_SS);
    float* sv  = (float*)(smem + SM_SV);
    float* sbi = (float*)(smem + SM_SB);

    if (tid < 64) { sv[tid] = attw[tid]; sbi[tid] = bap[tid]; }
    for (int idx = tid; idx < 64 * 64; idx += 256) {
        int o = idx >> 6, d = idx & 63;
        sW[o * 65 + d] = Wap[idx];
    }
    for (int u = tid; u < 64 * 16; u += 256) {
        int r = u >> 4, q = u & 15;
        *reinterpret_cast<float4*>(sXi + r * 64 + q * 4) =
            *reinterpret_cast<const float4*>(xb + (ti * 64 + r) * 64 + q * 4);
    }
    for (int u = tid; u < 64 * 16; u += 256) {
        int r = u >> 4, q = u & 15;
        float4 v4 = *reinterpret_cast<const float4*>(xb + (tj * 64 + r) * 64 + q * 4);
        uint2 pk = make_uint2(pack_bf16x2(v4.x, v4.y), pack_bf16x2(v4.z, v4.w));
        *reinterpret_cast<uint2*>(smem + SM_XJ + r * (XROW * 2) + q * 8) = pk;
    }
    __syncthreads();

    // per-thread epilogue constants: o0 = ot*8 + (lane&3)*2, ot in 0..7
    float vreg[16], breg[16];
    #pragma unroll
    for (int ot = 0; ot < 8; ++ot) {
        const int o0 = ot * 8 + (lane & 3) * 2;
        vreg[ot * 2]     = sv[o0];     breg[ot * 2]     = sbi[o0];
        vreg[ot * 2 + 1] = sv[o0 + 1]; breg[ot * 2 + 1] = sbi[o0 + 1];
    }
    const int lrow = lane & 15, lcol8 = (lane >> 4) * 8;

    for (int il = 0; il < 8; ++il) {
        const int i = w * 8 + il;
        const float* xi = sXi + i * 64;

        #pragma unroll
        for (int h = 0; h < 2; ++h) {
            // build B fragments for this o-half: 4 ot tiles
            uint32_t Breg[4][4][2];
            #pragma unroll
            for (int ot4 = 0; ot4 < 4; ++ot4) {
                const int o = (h * 4 + ot4) * 8 + (lane >> 2);
                const float* Wr = sW + o * 65;
                #pragma unroll
                for (int kt = 0; kt < 4; ++kt) {
                    const int d0 = kt * 16 + (lane & 3) * 2;
                    Breg[ot4][kt][0] = pack_bf16x2(Wr[d0]     * xi[d0],     Wr[d0 + 1] * xi[d0 + 1]);
                    Breg[ot4][kt][1] = pack_bf16x2(Wr[d0 + 8] * xi[d0 + 8], Wr[d0 + 9] * xi[d0 + 9]);
                }
            }

            #pragma unroll
            for (int jt = 0; jt < 4; ++jt) {
                uint32_t a[4][4];
                #pragma unroll
                for (int kt = 0; kt < 4; ++kt) {
                    uint32_t addr = sb32 + SM_XJ + (jt * 16 + lrow) * (XROW * 2) + (kt * 16 + lcol8) * 2;
                    ldmatrix_x4(a[kt][0], a[kt][1], a[kt][2], a[kt][3], addr);
                }
                float c[4][4];
                #pragma unroll
                for (int ot4 = 0; ot4 < 4; ++ot4) { c[ot4][0] = c[ot4][1] = c[ot4][2] = c[ot4][3] = 0.0f; }
                #pragma unroll
                for (int kt = 0; kt < 4; ++kt)
                    #pragma unroll
                    for (int ot4 = 0; ot4 < 4; ++ot4)
                        mma16816(c[ot4][0], c[ot4][1], c[ot4][2], c[ot4][3],
                                 a[kt][0], a[kt][1], a[kt][2], a[kt][3],
                                 Breg[ot4][kt][0], Breg[ot4][kt][1]);

                // epilogue (tree-reduced): 8 tanh per row-half
                float p00[4], p01[4], p10[4], p11[4];
                #pragma unroll
                for (int ot4 = 0; ot4 < 4; ++ot4) {
                    const int e = (h * 4 + ot4) * 2;
                    p00[ot4] = vreg[e]     * tanh_fast(c[ot4][0] + breg[e]);
                    p01[ot4] = vreg[e + 1] * tanh_fast(c[ot4][1] + breg[e + 1]);
                    p10[ot4] = vreg[e]     * tanh_fast(c[ot4][2] + breg[e]);
                    p11[ot4] = vreg[e + 1] * tanh_fast(c[ot4][3] + breg[e + 1]);
                }
                float s0 = ((p00[0] + p01[0]) + (p00[1] + p01[1]))
                         + ((p00[2] + p01[2]) + (p00[3] + p01[3]));
                float s1 = ((p10[0] + p11[0]) + (p10[1] + p11[1]))
                         + ((p10[2] + p11[2]) + (p10[3] + p11[3]));
                s0 += __shfl_xor_sync(0xffffffffu, s0, 1);
                s0 += __shfl_xor_sync(0xffffffffu, s0, 2);
                s1 += __shfl_xor_sync(0xffffffffu, s1, 1);
                s1 += __shfl_xor_sync(0xffffffffu, s1, 2);
                if ((lane & 3) == 0) {
                    float* d0 = sS + i * 65 + jt * 16 + (lane >> 2);
                    if (h == 0) { d0[0] = s0; d0[8] = s1; }
                    else        { d0[0] += s0; d0[8] += s1; }
                }
            }
        }
    }
    __syncthreads();

    {
        const int r = tid >> 2, cg = tid & 3;
        float* dst = g_scores + ((size_t)(b * 512 + ti * 64 + r)) * 512 + tj * 64 + cg * 16;
        #pragma unroll
        for (int q = 0; q < 4; ++q) {
            float4 vv = make_float4(sS[r * 65 + cg * 16 + q * 4 + 0],
                                    sS[r * 65 + cg * 16 + q * 4 + 1],
                                    sS[r * 65 + cg * 16 + q * 4 + 2],
                                    sS[r * 65 + cg * 16 + q * 4 + 3]);
            reinterpret_cast<float4*>(dst)[q] = vv;
        }
    }
    if (ti != tj) {
        const int jr = tid >> 2, cg = tid & 3;
        float* dst = g_scores + ((size_t)(b * 512 + tj * 64 + jr)) * 512 + ti * 64 + cg * 16;
        #pragma unroll
        for (int q = 0; q < 4; ++q) {
            float4 vv = make_float4(sS[(cg * 16 + q * 4 + 0) * 65 + jr],
                                    sS[(cg * 16 + q * 4 + 1) * 65 + jr],
                                    sS[(cg * 16 + q * 4 + 2) * 65 + jr],
                                    sS[(cg * 16 + q * 4 + 3) * 65 + jr]);
            reinterpret_cast<float4*>(dst)[q] = vv;
        }
    }
}

// ---------------- fused softmax+agg+proj kernel smem layout ------------------
#define EROW 520                      // bf16 elems per padded E row (1040 B)
#define SM_TX   0                     // 512*144 = 73728
#define SM_TE   73728                 // 64*1040 = 66560  (reused as sAgg after MMA)
#define SM_TINV 140288                // 256
#define SM_WW   140544                // 64*65*4 = 16640
#define SM_WO   157184                // 16640
#define SM_XF   173824                // 64*64*4 = 16384 (x fp32 rows)
#define SM_RS   190208                // 1024
#define SM_RQ   191232                // 1024
#define SMEM_T  192256

// ---------------------------------------------------------------------------
// Fused: softmax -> agg (MMA) -> x_out projections -> BN partials.
// CTA = (b, 64 i's). grid (8, 16), block 256.
// ---------------------------------------------------------------------------
__global__ void __launch_bounds__(256, 1)
smagg_kernel(const float* __restrict__ x,
             const float* __restrict__ Wwith, const float* __restrict__ bwith,
             const float* __restrict__ Wwo,   const float* __restrict__ bwo)
{
    extern __shared__ char smem[];
    const uint32_t sb32 = smem_u32(smem);
    const int tid = threadIdx.x, w = tid >> 5, lane = tid & 31;
    const int b = blockIdx.y, ibase = blockIdx.x * 64;
    const float* __restrict__ xb = x + (size_t)b * NN * DD;
    float* sinv = (float*)(smem + SM_TINV);
    float* sWw  = (float*)(smem + SM_WW);
    float* sWo  = (float*)(smem + SM_WO);
    float* sXf  = (float*)(smem + SM_XF);
    float* sAgg = (float*)(smem + SM_TE);     // valid after MMA phase
    float* rs   = (float*)(smem + SM_RS);
    float* rq   = (float*)(smem + SM_RQ);

    // ---- early loads: X bf16, weights, x fp32 rows ----
    for (int u = tid; u < 512 * 16; u += 256) {
        int r = u >> 4, q = u & 15;
        float4 v4 = *reinterpret_cast<const float4*>(xb + r * 64 + q * 4);
        uint2 pk = make_uint2(pack_bf16x2(v4.x, v4.y), pack_bf16x2(v4.z, v4.w));
        *reinterpret_cast<uint2*>(smem + SM_TX + r * (XROW * 2) + q * 8) = pk;
    }
    for (int idx = tid; idx < 64 * 64; idx += 256) {
        int o = idx >> 6, d = idx & 63;
        sWw[o * 65 + d] = Wwith[idx];
        sWo[o * 65 + d] = Wwo[idx];
    }
    for (int u = tid; u < 64 * 16; u += 256) {
        int r = u >> 4, q = u & 15;
        *reinterpret_cast<float4*>(sXf + r * 64 + q * 4) =
            *reinterpret_cast<const float4*>(xb + (ibase + r) * 64 + q * 4);
    }

    // ---- softmax: warp w handles rows il = w*8 + 0..7 ----
    for (int r = 0; r < 8; ++r) {
        const int il = w * 8 + r;
        const float* srow = g_scores + ((size_t)(b * 512 + ibase + il)) * 512;
        float v[16];
        #pragma unroll
        for (int q = 0; q < 16; ++q) v[q] = srow[lane + q * 32];
        float m = v[0];
        #pragma unroll
        for (int q = 1; q < 16; ++q) m = fmaxf(m, v[q]);
        #pragma unroll
        for (int o = 16; o; o >>= 1) m = fmaxf(m, __shfl_xor_sync(0xffffffffu, m, o));
        float sum = 0.0f;
        #pragma unroll
        for (int q = 0; q < 16; ++q) { v[q] = __expf(v[q] - m); sum += v[q]; }
        #pragma unroll
        for (int o = 16; o; o >>= 1) sum += __shfl_xor_sync(0xffffffffu, sum, o);
        #pragma unroll
        for (int q = 0; q < 16; ++q) {
            *reinterpret_cast<__nv_bfloat16*>(smem + SM_TE + il * (EROW * 2) + (lane + q * 32) * 2) =
                __float2bfloat16(v[q]);
        }
        if (lane == 0) sinv[il] = 1.0f / sum;
    }
    __syncthreads();

    // ---- agg MMA: warp w -> mt = w>>1 (16 i's), ntg = w&1 (32 d) ----
    const int mt = w >> 1, ntg = w & 1;
    const int i0 = mt * 16;
    float c[4][4];
    #pragma unroll
    for (int q = 0; q < 4; ++q) { c[q][0] = c[q][1] = c[q][2] = c[q][3] = 0.0f; }

    const int lrow = lane & 15, lcol8 = (lane >> 4) * 8;
    for (int kt = 0; kt < 32; ++kt) {
        const int k0 = kt * 16;
        uint32_t a0, a1, a2, a3;
        {
            uint32_t addr = sb32 + SM_TE + (i0 + lrow) * (EROW * 2) + (k0 + lcol8) * 2;
            ldmatrix_x4(a0, a1, a2, a3, addr);
        }
        const int kb = k0 + (lane & 3) * 2;
        #pragma unroll
        for (int q = 0; q < 4; ++q) {
            const int n = ntg * 32 + q * 8 + (lane >> 2);
            uint32_t lo0 = *reinterpret_cast<const unsigned short*>(smem + SM_TX + (kb)     * (XROW * 2) + n * 2);
            uint32_t hi0 = *reinterpret_cast<const unsigned short*>(smem + SM_TX + (kb + 1) * (XROW * 2) + n * 2);
            uint32_t lo1 = *reinterpret_cast<const unsigned short*>(smem + SM_TX + (kb + 8) * (XROW * 2) + n * 2);
            uint32_t hi1 = *reinterpret_cast<const unsigned short*>(smem + SM_TX + (kb + 9) * (XROW * 2) + n * 2);
            uint32_t b0 = lo0 | (hi0 << 16);
            uint32_t b1 = lo1 | (hi1 << 16);
            mma16816(c[q][0], c[q][1], c[q][2], c[q][3], a0, a1, a2, a3, b0, b1);
        }
    }
    __syncthreads();   // E no longer needed; TE region becomes sAgg

    // ---- write normalized agg into smem ----
    {
        const int r0 = i0 + (lane >> 2), r1 = r0 + 8;
        const float inv0 = sinv[r0], inv1 = sinv[r1];
        #pragma unroll
        for (int q = 0; q < 4; ++q) {
            const int d0 = ntg * 32 + q * 8 + (lane & 3) * 2;
            sAgg[r0 * 64 + d0]     = c[q][0] * inv0;
            sAgg[r0 * 64 + d0 + 1] = c[q][1] * inv0;
            sAgg[r1 * 64 + d0]     = c[q][2] * inv1;
            sAgg[r1 * 64 + d0 + 1] = c[q][3] * inv1;
        }
    }
    __syncthreads();

    // ---- projections + BN partials (former stage2, 64 rows) ----
    {
        const int o = tid & 63, rg = tid >> 6;     // 4 groups x 16 rows
        const float bias = bwith[o] + bwo[o];
        float lsum = 0.0f, lsq = 0.0f;
        for (int rr = 0; rr < 16; ++rr) {
            const int r = rg * 16 + rr;
            float acc = bias;
            #pragma unroll 8
            for (int d = 0; d < 64; ++d)
                acc += sAgg[r * 64 + d] * sWw[o * 65 + d]
                     + sXf [r * 64 + d] * sWo[o * 65 + d];
            g_xout[(size_t)(b * 512 + ibase + r) * 64 + o] = acc;
            lsum += acc;
            lsq  = fmaf(acc, acc, lsq);
        }
        rs[rg * 64 + o] = lsum;
        rq[rg * 64 + o] = lsq;
    }
    __syncthreads();
    if (tid < 64) {
        float s = rs[tid] + rs[64 + tid] + rs[128 + tid] + rs[192 + tid];
        float q = rq[tid] + rq[64 + tid] + rq[128 + tid] + rq[192 + tid];
        const int cta = blockIdx.y * 8 + blockIdx.x;   // 0..127
        g_ps[cta * 64 + tid] = s;
        g_pq[cta * 64 + tid] = q;
    }
}

// ---------------------------------------------------------------------------
// Stage 3a: one block per channel; 128 partials each. grid 64 x 128 threads.
// ---------------------------------------------------------------------------
__global__ void __launch_bounds__(128)
stage3a_kernel()
{
    __shared__ float rs[128], rq[128];
    const int o = blockIdx.x, t = threadIdx.x;
    rs[t] = g_ps[t * 64 + o];
    rq[t] = g_pq[t * 64 + o];
    __syncthreads();
    if (t < 32) {
        float ss = rs[t] + rs[t + 32] + rs[t + 64] + rs[t + 96];
        float qq = rq[t] + rq[t + 32] + rq[t + 64] + rq[t + 96];
        #pragma unroll
        for (int off = 16; off; off >>= 1) {
            ss += __shfl_xor_sync(0xffffffffu, ss, off);
            qq += __shfl_xor_sync(0xffffffffu, qq, off);
        }
        if (t == 0) {
            const float mean = ss * (1.0f / 8192.0f);
            const float var  = qq * (1.0f / 8192.0f) - mean * mean;
            g_mean[o] = mean;
            g_istd[o] = rsqrtf(var + BN_EPS);
        }
    }
}

__global__ void __launch_bounds__(512)
stage3b_kernel(const float* __restrict__ gamma, const float* __restrict__ beta,
               float* __restrict__ out)
{
    const int idx = blockIdx.x * 512 + threadIdx.x;
    const int o = idx & 63;
    float v = g_xout[idx];
    float n = (v - g_mean[o]) * g_istd[o] * gamma[o] + beta[o];
    const float alpha = 1.6732632423543772f;
    const float lam   = 1.0507009873554805f;
    out[idx] = (n > 0.0f) ? lam * n : lam * alpha * expm1f(n);
}

// ---------------------------------------------------------------------------
extern "C" void kernel_launch(void* const* d_in, const int* in_sizes, int n_in,
                              void* d_out, int out_size)
{
    const float* x     = (const float*)d_in[0];
    const float* Wap   = (const float*)d_in[1];
    const float* bap   = (const float*)d_in[2];
    const float* attw  = (const float*)d_in[3];
    const float* Wwith = (const float*)d_in[4];
    const float* bwith = (const float*)d_in[5];
    const float* Wwo   = (const float*)d_in[6];
    const float* bwo   = (const float*)d_in[7];
    const float* gamma = (const float*)d_in[8];
    const float* beta  = (const float*)d_in[9];
    float* out = (float*)d_out;

    cudaFuncSetAttribute(score_kernel,
                         cudaFuncAttributeMaxDynamicSharedMemorySize, SMEM_S);
    cudaFuncSetAttribute(smagg_kernel,
                         cudaFuncAttributeMaxDynamicSharedMemorySize, SMEM_T);

    dim3 gs(36, 16);
    score_kernel<<<gs, 256, SMEM_S>>>(x, Wap, bap, attw);
    dim3 gt(8, 16);
    smagg_kernel<<<gt, 256, SMEM_T>>>(x, Wwith, bwith, Wwo, bwo);
    stage3a_kernel<<<64, 128>>>();
    stage3b_kernel<<<(BB * NN * DD) / 512, 512>>>(gamma, beta, out);
}

// round 13
// speedup vs baseline: 7.4139x; 1.0028x over previous
#include <cuda_runtime.h>
#include <cuda_bf16.h>
#include <cuda_fp16.h>
#include <cstdint>
#include <stdint.h>
#include <math.h>

#define BB 16
#define NN 512
#define DD 64
#define BN_EPS 1e-5f

// ---------------- scratch ---------------------------------------------------
__device__ float g_scores[BB * NN * NN];   // (B,N,N) raw scores (symmetric)
__device__ float g_xout[BB * NN * DD];
__device__ float g_ps  [128 * 64];
__device__ float g_pq  [128 * 64];
__device__ float g_mean[64];
__device__ float g_istd[64];

// ---------------- helpers ----------------------------------------------------
__device__ __forceinline__ uint32_t smem_u32(const void* p) {
    uint32_t a;
    asm("{ .reg .u64 t; cvta.to.shared.u64 t, %1; cvt.u32.u64 %0, t; }" : "=r"(a) : "l"(p));
    return a;
}
__device__ __forceinline__ float tanh_fast(float x) {
    float y; asm("tanh.approx.f32 %0, %1;" : "=f"(y) : "f"(x)); return y;
}
__device__ __forceinline__ uint32_t pack_bf16x2(float lo, float hi) {
    __nv_bfloat162 p = __float22bfloat162_rn(make_float2(lo, hi));
    return *reinterpret_cast<uint32_t*>(&p);
}
__device__ __forceinline__ uint32_t pack_f16x2(float lo, float hi) {
    __half2 p = __float22half2_rn(make_float2(lo, hi));
    return *reinterpret_cast<uint32_t*>(&p);
}
// bf16 MMA, f32 accumulate (agg path — precision-critical)
__device__ __forceinline__ void mma16816(float& c0, float& c1, float& c2, float& c3,
                                         uint32_t a0, uint32_t a1, uint32_t a2, uint32_t a3,
                                         uint32_t b0, uint32_t b1) {
    asm volatile("mma.sync.aligned.m16n8k16.row.col.f32.bf16.bf16.f32 "
                 "{%0,%1,%2,%3}, {%4,%5,%6,%7}, {%8,%9}, {%0,%1,%2,%3};"
                 : "+f"(c0), "+f"(c1), "+f"(c2), "+f"(c3)
                 : "r"(a0), "r"(a1), "r"(a2), "r"(a3), "r"(b0), "r"(b1));
}
// fp16 MMA, f16 accumulate (score path — 2x rate on legacy tensor pipe)
__device__ __forceinline__ void mma16816_h(uint32_t& c0, uint32_t& c1,
                                           uint32_t a0, uint32_t a1, uint32_t a2, uint32_t a3,
                                           uint32_t b0, uint32_t b1) {
    asm volatile("mma.sync.aligned.m16n8k16.row.col.f16.f16.f16.f16 "
                 "{%0,%1}, {%2,%3,%4,%5}, {%6,%7}, {%0,%1};"
                 : "+r"(c0), "+r"(c1)
                 : "r"(a0), "r"(a1), "r"(a2), "r"(a3), "r"(b0), "r"(b1));
}
__device__ __forceinline__ void ldmatrix_x4(uint32_t& r0, uint32_t& r1, uint32_t& r2, uint32_t& r3,
                                            uint32_t addr) {
    asm volatile("ldmatrix.sync.aligned.m8n8.x4.shared.b16 {%0,%1,%2,%3}, [%4];"
                 : "=r"(r0), "=r"(r1), "=r"(r2), "=r"(r3) : "r"(addr));
}
__device__ __forceinline__ void ldmatrix_x4_trans(uint32_t& r0, uint32_t& r1, uint32_t& r2, uint32_t& r3,
                                                  uint32_t addr) {
    asm volatile("ldmatrix.sync.aligned.m8n8.x4.trans.shared.b16 {%0,%1,%2,%3}, [%4];"
                 : "=r"(r0), "=r"(r1), "=r"(r2), "=r"(r3) : "r"(addr));
}

// ---------------- score kernel smem layout (bytes) ---------------------------
#define XROW 72                       // b16 elems per padded row (144 B)
#define SM_XJ   0                     // 64*144 = 9216
#define SM_W    9216                  // 64*65*4 = 16640
#define SM_XI   25856                 // 64*64*4 = 16384
#define SM_SS   42240                 // 64*65*4 = 16640
#define SM_SV   58880                 // 256
#define SM_SB   59136                 // 256
#define SMEM_S  59392

// ---------------------------------------------------------------------------
// Score kernel: CTA = (batch b, upper-tri 64x64 tile pair (ti<=tj)).
// fp16 inputs + fp16 accumulate MMA (2x legacy HMMA rate), o-dim split in two
// halves, 2 CTAs/SM. grid (36, 16), block 256.
// ---------------------------------------------------------------------------
__global__ void __launch_bounds__(256, 2)
score_kernel(const float* __restrict__ x, const float* __restrict__ Wap,
             const float* __restrict__ bap, const float* __restrict__ attw)
{
    extern __shared__ char smem[];
    const uint32_t sb32 = smem_u32(smem);
    const int tid = threadIdx.x, w = tid >> 5, lane = tid & 31;
    const int b = blockIdx.y;

    int p = blockIdx.x, ti = 0;
    while (p >= 8 - ti) { p -= 8 - ti; ++ti; }
    const int tj = ti + p;

    const float* __restrict__ xb = x + (size_t)b * NN * DD;

    float* sW  = (float*)(smem + SM_W);
    float* sXi = (float*)(smem + SM_XI);
    float* sS  = (float*)(smem + SM_SS);
    float* sv  = (float*)(smem + SM_SV);
    float* sbi = (float*)(smem + SM_SB);

    if (tid < 64) { sv[tid] = attw[tid]; sbi[tid] = bap[tid]; }
    for (int idx = tid; idx < 64 * 64; idx += 256) {
        int o = idx >> 6, d = idx & 63;
        sW[o * 65 + d] = Wap[idx];
    }
    for (int u = tid; u < 64 * 16; u += 256) {
        int r = u >> 4, q = u & 15;
        *reinterpret_cast<float4*>(sXi + r * 64 + q * 4) =
            *reinterpret_cast<const float4*>(xb + (ti * 64 + r) * 64 + q * 4);
    }
    for (int u = tid; u < 64 * 16; u += 256) {     // Xj -> fp16 padded rows
        int r = u >> 4, q = u & 15;
        float4 v4 = *reinterpret_cast<const float4*>(xb + (tj * 64 + r) * 64 + q * 4);
        uint2 pk = make_uint2(pack_f16x2(v4.x, v4.y), pack_f16x2(v4.z, v4.w));
        *reinterpret_cast<uint2*>(smem + SM_XJ + r * (XROW * 2) + q * 8) = pk;
    }
    __syncthreads();

    // per-thread epilogue constants: o0 = ot*8 + (lane&3)*2, ot in 0..7
    float vreg[16], breg[16];
    #pragma unroll
    for (int ot = 0; ot < 8; ++ot) {
        const int o0 = ot * 8 + (lane & 3) * 2;
        vreg[ot * 2]     = sv[o0];     breg[ot * 2]     = sbi[o0];
        vreg[ot * 2 + 1] = sv[o0 + 1]; breg[ot * 2 + 1] = sbi[o0 + 1];
    }
    const int lrow = lane & 15, lcol8 = (lane >> 4) * 8;

    for (int il = 0; il < 8; ++il) {
        const int i = w * 8 + il;
        const float* xi = sXi + i * 64;

        #pragma unroll
        for (int h = 0; h < 2; ++h) {
            // build B fragments (fp16) for this o-half: 4 ot tiles
            uint32_t Breg[4][4][2];
            #pragma unroll
            for (int ot4 = 0; ot4 < 4; ++ot4) {
                const int o = (h * 4 + ot4) * 8 + (lane >> 2);
                const float* Wr = sW + o * 65;
                #pragma unroll
                for (int kt = 0; kt < 4; ++kt) {
                    const int d0 = kt * 16 + (lane & 3) * 2;
                    Breg[ot4][kt][0] = pack_f16x2(Wr[d0]     * xi[d0],     Wr[d0 + 1] * xi[d0 + 1]);
                    Breg[ot4][kt][1] = pack_f16x2(Wr[d0 + 8] * xi[d0 + 8], Wr[d0 + 9] * xi[d0 + 9]);
                }
            }

            #pragma unroll
            for (int jt = 0; jt < 4; ++jt) {
                uint32_t a[4][4];
                #pragma unroll
                for (int kt = 0; kt < 4; ++kt) {
                    uint32_t addr = sb32 + SM_XJ + (jt * 16 + lrow) * (XROW * 2) + (kt * 16 + lcol8) * 2;
                    ldmatrix_x4(a[kt][0], a[kt][1], a[kt][2], a[kt][3], addr);
                }
                uint32_t c[4][2];
                #pragma unroll
                for (int ot4 = 0; ot4 < 4; ++ot4) { c[ot4][0] = 0u; c[ot4][1] = 0u; }
                #pragma unroll
                for (int kt = 0; kt < 4; ++kt)
                    #pragma unroll
                    for (int ot4 = 0; ot4 < 4; ++ot4)
                        mma16816_h(c[ot4][0], c[ot4][1],
                                   a[kt][0], a[kt][1], a[kt][2], a[kt][3],
                                   Breg[ot4][kt][0], Breg[ot4][kt][1]);

                // epilogue (tree-reduced): 8 tanh per row-half
                float p00[4], p01[4], p10[4], p11[4];
                #pragma unroll
                for (int ot4 = 0; ot4 < 4; ++ot4) {
                    const int e = (h * 4 + ot4) * 2;
                    float2 lo = __half22float2(*reinterpret_cast<__half2*>(&c[ot4][0]));
                    float2 hi = __half22float2(*reinterpret_cast<__half2*>(&c[ot4][1]));
                    p00[ot4] = vreg[e]     * tanh_fast(lo.x + breg[e]);
                    p01[ot4] = vreg[e + 1] * tanh_fast(lo.y + breg[e + 1]);
                    p10[ot4] = vreg[e]     * tanh_fast(hi.x + breg[e]);
                    p11[ot4] = vreg[e + 1] * tanh_fast(hi.y + breg[e + 1]);
                }
                float s0 = ((p00[0] + p01[0]) + (p00[1] + p01[1]))
                         + ((p00[2] + p01[2]) + (p00[3] + p01[3]));
                float s1 = ((p10[0] + p11[0]) + (p10[1] + p11[1]))
                         + ((p10[2] + p11[2]) + (p10[3] + p11[3]));
                s0 += __shfl_xor_sync(0xffffffffu, s0, 1);
                s0 += __shfl_xor_sync(0xffffffffu, s0, 2);
                s1 += __shfl_xor_sync(0xffffffffu, s1, 1);
                s1 += __shfl_xor_sync(0xffffffffu, s1, 2);
                if ((lane & 3) == 0) {
                    float* d0 = sS + i * 65 + jt * 16 + (lane >> 2);
                    if (h == 0) { d0[0] = s0; d0[8] = s1; }
                    else        { d0[0] += s0; d0[8] += s1; }
                }
            }
        }
    }
    __syncthreads();

    {
        const int r = tid >> 2, cg = tid & 3;
        float* dst = g_scores + ((size_t)(b * 512 + ti * 64 + r)) * 512 + tj * 64 + cg * 16;
        #pragma unroll
        for (int q = 0; q < 4; ++q) {
            float4 vv = make_float4(sS[r * 65 + cg * 16 + q * 4 + 0],
                                    sS[r * 65 + cg * 16 + q * 4 + 1],
                                    sS[r * 65 + cg * 16 + q * 4 + 2],
                                    sS[r * 65 + cg * 16 + q * 4 + 3]);
            reinterpret_cast<float4*>(dst)[q] = vv;
        }
    }
    if (ti != tj) {
        const int jr = tid >> 2, cg = tid & 3;
        float* dst = g_scores + ((size_t)(b * 512 + tj * 64 + jr)) * 512 + ti * 64 + cg * 16;
        #pragma unroll
        for (int q = 0; q < 4; ++q) {
            float4 vv = make_float4(sS[(cg * 16 + q * 4 + 0) * 65 + jr],
                                    sS[(cg * 16 + q * 4 + 1) * 65 + jr],
                                    sS[(cg * 16 + q * 4 + 2) * 65 + jr],
                                    sS[(cg * 16 + q * 4 + 3) * 65 + jr]);
            reinterpret_cast<float4*>(dst)[q] = vv;
        }
    }
}

// ---------------- fused softmax+agg+proj kernel smem layout ------------------
#define EROW 520                      // bf16 elems per padded E row (1040 B)
#define SM_TX   0                     // 512*144 = 73728
#define SM_TE   73728                 // 64*1040 = 66560  (reused as sAgg after MMA)
#define SM_TINV 140288                // 256
#define SM_WW   140544                // 64*65*4 = 16640
#define SM_WO   157184                // 16640
#define SM_XF   173824                // 64*64*4 = 16384 (x fp32 rows)
#define SM_RS   190208                // 1024
#define SM_RQ   191232                // 1024
#define SMEM_T  192256

// ---------------------------------------------------------------------------
// Fused: softmax -> agg (MMA, trans-ldmatrix B) -> projections -> BN partials.
// CTA = (b, 64 i's). grid (8, 16), block 256.
// ---------------------------------------------------------------------------
__global__ void __launch_bounds__(256, 1)
smagg_kernel(const float* __restrict__ x,
             const float* __restrict__ Wwith, const float* __restrict__ bwith,
             const float* __restrict__ Wwo,   const float* __restrict__ bwo)
{
    extern __shared__ char smem[];
    const uint32_t sb32 = smem_u32(smem);
    const int tid = threadIdx.x, w = tid >> 5, lane = tid & 31;
    const int b = blockIdx.y, ibase = blockIdx.x * 64;
    const float* __restrict__ xb = x + (size_t)b * NN * DD;
    float* sinv = (float*)(smem + SM_TINV);
    float* sWw  = (float*)(smem + SM_WW);
    float* sWo  = (float*)(smem + SM_WO);
    float* sXf  = (float*)(smem + SM_XF);
    float* sAgg = (float*)(smem + SM_TE);     // valid after MMA phase
    float* rs   = (float*)(smem + SM_RS);
    float* rq   = (float*)(smem + SM_RQ);

    // ---- early loads: X bf16, weights, x fp32 rows ----
    for (int u = tid; u < 512 * 16; u += 256) {
        int r = u >> 4, q = u & 15;
        float4 v4 = *reinterpret_cast<const float4*>(xb + r * 64 + q * 4);
        uint2 pk = make_uint2(pack_bf16x2(v4.x, v4.y), pack_bf16x2(v4.z, v4.w));
        *reinterpret_cast<uint2*>(smem + SM_TX + r * (XROW * 2) + q * 8) = pk;
    }
    for (int idx = tid; idx < 64 * 64; idx += 256) {
        int o = idx >> 6, d = idx & 63;
        sWw[o * 65 + d] = Wwith[idx];
        sWo[o * 65 + d] = Wwo[idx];
    }
    for (int u = tid; u < 64 * 16; u += 256) {
        int r = u >> 4, q = u & 15;
        *reinterpret_cast<float4*>(sXf + r * 64 + q * 4) =
            *reinterpret_cast<const float4*>(xb + (ibase + r) * 64 + q * 4);
    }

    // ---- softmax: warp w handles rows il = w*8 + 0..7 ----
    for (int r = 0; r < 8; ++r) {
        const int il = w * 8 + r;
        const float* srow = g_scores + ((size_t)(b * 512 + ibase + il)) * 512;
        float v[16];
        #pragma unroll
        for (int q = 0; q < 16; ++q) v[q] = srow[lane + q * 32];
        float m = v[0];
        #pragma unroll
        for (int q = 1; q < 16; ++q) m = fmaxf(m, v[q]);
        #pragma unroll
        for (int o = 16; o; o >>= 1) m = fmaxf(m, __shfl_xor_sync(0xffffffffu, m, o));
        float sum = 0.0f;
        #pragma unroll
        for (int q = 0; q < 16; ++q) { v[q] = __expf(v[q] - m); sum += v[q]; }
        #pragma unroll
        for (int o = 16; o; o >>= 1) sum += __shfl_xor_sync(0xffffffffu, sum, o);
        #pragma unroll
        for (int q = 0; q < 16; ++q) {
            *reinterpret_cast<__nv_bfloat16*>(smem + SM_TE + il * (EROW * 2) + (lane + q * 32) * 2) =
                __float2bfloat16(v[q]);
        }
        if (lane == 0) sinv[il] = 1.0f / sum;
    }
    __syncthreads();

    // ---- agg MMA: warp w -> mt = w>>1 (16 i's), ntg = w&1 (32 d) ----
    const int mt = w >> 1, ntg = w & 1;
    const int i0 = mt * 16;
    float c[4][4];
    #pragma unroll
    for (int q = 0; q < 4; ++q) { c[q][0] = c[q][1] = c[q][2] = c[q][3] = 0.0f; }

    const int lrow = lane & 15, lcol8 = (lane >> 4) * 8;
    for (int kt = 0; kt < 32; ++kt) {
        const int k0 = kt * 16;
        uint32_t a0, a1, a2, a3;
        {
            uint32_t addr = sb32 + SM_TE + (i0 + lrow) * (EROW * 2) + (k0 + lcol8) * 2;
            ldmatrix_x4(a0, a1, a2, a3, addr);
        }
        // B fragments via trans-ldmatrix on X[j][d] (k=j rows, n=d cols)
        uint32_t bf[8];
        #pragma unroll
        for (int g = 0; g < 2; ++g) {
            const int n0 = ntg * 32 + g * 16;
            uint32_t addr = sb32 + SM_TX + (k0 + lrow) * (XROW * 2) + (n0 + lcol8) * 2;
            ldmatrix_x4_trans(bf[g * 4 + 0], bf[g * 4 + 1], bf[g * 4 + 2], bf[g * 4 + 3], addr);
        }
        #pragma unroll
        for (int q = 0; q < 4; ++q)
            mma16816(c[q][0], c[q][1], c[q][2], c[q][3], a0, a1, a2, a3,
                     bf[q * 2], bf[q * 2 + 1]);
    }
    __syncthreads();   // E no longer needed; TE region becomes sAgg

    // ---- write normalized agg into smem ----
    {
        const int r0 = i0 + (lane >> 2), r1 = r0 + 8;
        const float inv0 = sinv[r0], inv1 = sinv[r1];
        #pragma unroll
        for (int q = 0; q < 4; ++q) {
            const int d0 = ntg * 32 + q * 8 + (lane & 3) * 2;
            sAgg[r0 * 64 + d0]     = c[q][0] * inv0;
            sAgg[r0 * 64 + d0 + 1] = c[q][1] * inv0;
            sAgg[r1 * 64 + d0]     = c[q][2] * inv1;
            sAgg[r1 * 64 + d0 + 1] = c[q][3] * inv1;
        }
    }
    __syncthreads();

    // ---- projections + BN partials (former stage2, 64 rows) ----
    {
        const int o = tid & 63, rg = tid >> 6;     // 4 groups x 16 rows
        const float bias = bwith[o] + bwo[o];
        float lsum = 0.0f, lsq = 0.0f;
        for (int rr = 0; rr < 16; ++rr) {
            const int r = rg * 16 + rr;
            float acc = bias;
            #pragma unroll 8
            for (int d = 0; d < 64; ++d)
                acc += sAgg[r * 64 + d] * sWw[o * 65 + d]
                     + sXf [r * 64 + d] * sWo[o * 65 + d];
            g_xout[(size_t)(b * 512 + ibase + r) * 64 + o] = acc;
            lsum += acc;
            lsq  = fmaf(acc, acc, lsq);
        }
        rs[rg * 64 + o] = lsum;
        rq[rg * 64 + o] = lsq;
    }
    __syncthreads();
    if (tid < 64) {
        float s = rs[tid] + rs[64 + tid] + rs[128 + tid] + rs[192 + tid];
        float q = rq[tid] + rq[64 + tid] + rq[128 + tid] + rq[192 + tid];
        const int cta = blockIdx.y * 8 + blockIdx.x;   // 0..127
        g_ps[cta * 64 + tid] = s;
        g_pq[cta * 64 + tid] = q;
    }
}

// ---------------------------------------------------------------------------
// Stage 3a: one block per channel; 128 partials each. grid 64 x 128 threads.
// ---------------------------------------------------------------------------
__global__ void __launch_bounds__(128)
stage3a_kernel()
{
    __shared__ float rs[128], rq[128];
    const int o = blockIdx.x, t = threadIdx.x;
    rs[t] = g_ps[t * 64 + o];
    rq[t] = g_pq[t * 64 + o];
    __syncthreads();
    if (t < 32) {
        float ss = rs[t] + rs[t + 32] + rs[t + 64] + rs[t + 96];
        float qq = rq[t] + rq[t + 32] + rq[t + 64] + rq[t + 96];
        #pragma unroll
        for (int off = 16; off; off >>= 1) {
            ss += __shfl_xor_sync(0xffffffffu, ss, off);
            qq += __shfl_xor_sync(0xffffffffu, qq, off);
        }
        if (t == 0) {
            const float mean = ss * (1.0f / 8192.0f);
            const float var  = qq * (1.0f / 8192.0f) - mean * mean;
            g_mean[o] = mean;
            g_istd[o] = rsqrtf(var + BN_EPS);
        }
    }
}

__global__ void __launch_bounds__(512)
stage3b_kernel(const float* __restrict__ gamma, const float* __restrict__ beta,
               float* __restrict__ out)
{
    const int idx = blockIdx.x * 512 + threadIdx.x;
    const int o = idx & 63;
    float v = g_xout[idx];
    float n = (v - g_mean[o]) * g_istd[o] * gamma[o] + beta[o];
    const float alpha = 1.6732632423543772f;
    const float lam   = 1.0507009873554805f;
    out[idx] = (n > 0.0f) ? lam * n : lam * alpha * expm1f(n);
}

// ---------------------------------------------------------------------------
extern "C" void kernel_launch(void* const* d_in, const int* in_sizes, int n_in,
                              void* d_out, int out_size)
{
    const float* x     = (const float*)d_in[0];
    const float* Wap   = (const float*)d_in[1];
    const float* bap   = (const float*)d_in[2];
    const float* attw  = (const float*)d_in[3];
    const float* Wwith = (const float*)d_in[4];
    const float* bwith = (const float*)d_in[5];
    const float* Wwo   = (const float*)d_in[6];
    const float* bwo   = (const float*)d_in[7];
    const float* gamma = (const float*)d_in[8];
    const float* beta  = (const float*)d_in[9];
    float* out = (float*)d_out;

    cudaFuncSetAttribute(score_kernel,
                         cudaFuncAttributeMaxDynamicSharedMemorySize, SMEM_S);
    cudaFuncSetAttribute(smagg_kernel,
                         cudaFuncAttributeMaxDynamicSharedMemorySize, SMEM_T);

    dim3 gs(36, 16);
    score_kernel<<<gs, 256, SMEM_S>>>(x, Wap, bap, attw);
    dim3 gt(8, 16);
    smagg_kernel<<<gt, 256, SMEM_T>>>(x, Wwith, bwith, Wwo, bwo);
    stage3a_kernel<<<64, 128>>>();
    stage3b_kernel<<<(BB * NN * DD) / 512, 512>>>(gamma, beta, out);
}

// round 14
// speedup vs baseline: 10.0969x; 1.3619x over previous
#include <cuda_runtime.h>
#include <cuda_bf16.h>
#include <cuda_fp16.h>
#include <cstdint>
#include <stdint.h>
#include <math.h>

#define BB 16
#define NN 512
#define DD 64
#define BN_EPS 1e-5f

// ---------------- scratch ---------------------------------------------------
__device__ float g_scores[BB * NN * NN];   // (B,N,N) raw scores (symmetric)
__device__ float g_xout[BB * NN * DD];
__device__ float g_ps  [128 * 64];
__device__ float g_pq  [128 * 64];
__device__ float g_mean[64];
__device__ float g_istd[64];

// ---------------- helpers ----------------------------------------------------
__device__ __forceinline__ uint32_t smem_u32(const void* p) {
    uint32_t a;
    asm("{ .reg .u64 t; cvta.to.shared.u64 t, %1; cvt.u32.u64 %0, t; }" : "=r"(a) : "l"(p));
    return a;
}
__device__ __forceinline__ float tanh_fast(float x) {
    float y; asm("tanh.approx.f32 %0, %1;" : "=f"(y) : "f"(x)); return y;
}
__device__ __forceinline__ uint32_t tanh_h2(uint32_t x) {
    uint32_t y; asm("tanh.approx.f16x2 %0, %1;" : "=r"(y) : "r"(x)); return y;
}
__device__ __forceinline__ uint32_t hadd2u(uint32_t a, uint32_t b) {
    __half2 r = __hadd2(*reinterpret_cast<__half2*>(&a), *reinterpret_cast<__half2*>(&b));
    return *reinterpret_cast<uint32_t*>(&r);
}
__device__ __forceinline__ uint32_t hmul2u(uint32_t a, uint32_t b) {
    __half2 r = __hmul2(*reinterpret_cast<__half2*>(&a), *reinterpret_cast<__half2*>(&b));
    return *reinterpret_cast<uint32_t*>(&r);
}
__device__ __forceinline__ float2 h2f2(uint32_t a) {
    return __half22float2(*reinterpret_cast<__half2*>(&a));
}
__device__ __forceinline__ uint32_t pack_bf16x2(float lo, float hi) {
    __nv_bfloat162 p = __float22bfloat162_rn(make_float2(lo, hi));
    return *reinterpret_cast<uint32_t*>(&p);
}
__device__ __forceinline__ uint32_t pack_f16x2(float lo, float hi) {
    __half2 p = __float22half2_rn(make_float2(lo, hi));
    return *reinterpret_cast<uint32_t*>(&p);
}
// bf16 MMA, f32 accumulate (agg path — precision-critical)
__device__ __forceinline__ void mma16816(float& c0, float& c1, float& c2, float& c3,
                                         uint32_t a0, uint32_t a1, uint32_t a2, uint32_t a3,
                                         uint32_t b0, uint32_t b1) {
    asm volatile("mma.sync.aligned.m16n8k16.row.col.f32.bf16.bf16.f32 "
                 "{%0,%1,%2,%3}, {%4,%5,%6,%7}, {%8,%9}, {%0,%1,%2,%3};"
                 : "+f"(c0), "+f"(c1), "+f"(c2), "+f"(c3)
                 : "r"(a0), "r"(a1), "r"(a2), "r"(a3), "r"(b0), "r"(b1));
}
// fp16 MMA, f16 accumulate (score path)
__device__ __forceinline__ void mma16816_h(uint32_t& c0, uint32_t& c1,
                                           uint32_t a0, uint32_t a1, uint32_t a2, uint32_t a3,
                                           uint32_t b0, uint32_t b1) {
    asm volatile("mma.sync.aligned.m16n8k16.row.col.f16.f16.f16.f16 "
                 "{%0,%1}, {%2,%3,%4,%5}, {%6,%7}, {%0,%1};"
                 : "+r"(c0), "+r"(c1)
                 : "r"(a0), "r"(a1), "r"(a2), "r"(a3), "r"(b0), "r"(b1));
}
__device__ __forceinline__ void ldmatrix_x4(uint32_t& r0, uint32_t& r1, uint32_t& r2, uint32_t& r3,
                                            uint32_t addr) {
    asm volatile("ldmatrix.sync.aligned.m8n8.x4.shared.b16 {%0,%1,%2,%3}, [%4];"
                 : "=r"(r0), "=r"(r1), "=r"(r2), "=r"(r3) : "r"(addr));
}
__device__ __forceinline__ void ldmatrix_x4_trans(uint32_t& r0, uint32_t& r1, uint32_t& r2, uint32_t& r3,
                                                  uint32_t addr) {
    asm volatile("ldmatrix.sync.aligned.m8n8.x4.trans.shared.b16 {%0,%1,%2,%3}, [%4];"
                 : "=r"(r0), "=r"(r1), "=r"(r2), "=r"(r3) : "r"(addr));
}

// ---------------- score kernel smem layout (bytes) ---------------------------
#define XROW 72                       // b16 elems per padded row (144 B)
#define SM_XJ   0                     // 64*144 = 9216   (Xj fp16)
#define SM_XIH  9216                  // 64*144 = 9216   (Xi fp16)
#define SM_W    18432                 // 64*65*4 = 16640
#define SM_SS   35072                 // 64*65*4 = 16640
#define SM_SV   51712                 // 256
#define SM_SB   51968                 // 256
#define SMEM_S  52224

// ---------------------------------------------------------------------------
// Score kernel: CTA = (batch b, upper-tri 64x64 tile pair (ti<=tj)).
// C = (Xj ⊙ xi) @ W^T : W is the loop-invariant B operand (packed once per
// o-half); A = Xj fragments ldmatrix'd once per (h,jt) and rescaled per i with
// xi (HMUL2). fp16 MMA + f16x2 tanh epilogue. 2 CTAs/SM. grid (36,16), blk 256.
// ---------------------------------------------------------------------------
__global__ void __launch_bounds__(256, 2)
score_kernel(const float* __restrict__ x, const float* __restrict__ Wap,
             const float* __restrict__ bap, const float* __restrict__ attw)
{
    extern __shared__ char smem[];
    const uint32_t sb32 = smem_u32(smem);
    const int tid = threadIdx.x, w = tid >> 5, lane = tid & 31;
    const int b = blockIdx.y;

    int p = blockIdx.x, ti = 0;
    while (p >= 8 - ti) { p -= 8 - ti; ++ti; }
    const int tj = ti + p;

    const float* __restrict__ xb = x + (size_t)b * NN * DD;

    float* sW  = (float*)(smem + SM_W);
    float* sS  = (float*)(smem + SM_SS);
    float* sv  = (float*)(smem + SM_SV);
    float* sbi = (float*)(smem + SM_SB);

    if (tid < 64) { sv[tid] = attw[tid]; sbi[tid] = bap[tid]; }
    for (int idx = tid; idx < 64 * 64; idx += 256) {
        int o = idx >> 6, d = idx & 63;
        sW[o * 65 + d] = Wap[idx];
    }
    for (int u = tid; u < 64 * 16; u += 256) {     // Xi -> fp16 padded rows
        int r = u >> 4, q = u & 15;
        float4 v4 = *reinterpret_cast<const float4*>(xb + (ti * 64 + r) * 64 + q * 4);
        uint2 pk = make_uint2(pack_f16x2(v4.x, v4.y), pack_f16x2(v4.z, v4.w));
        *reinterpret_cast<uint2*>(smem + SM_XIH + r * (XROW * 2) + q * 8) = pk;
    }
    for (int u = tid; u < 64 * 16; u += 256) {     // Xj -> fp16 padded rows
        int r = u >> 4, q = u & 15;
        float4 v4 = *reinterpret_cast<const float4*>(xb + (tj * 64 + r) * 64 + q * 4);
        uint2 pk = make_uint2(pack_f16x2(v4.x, v4.y), pack_f16x2(v4.z, v4.w));
        *reinterpret_cast<uint2*>(smem + SM_XJ + r * (XROW * 2) + q * 8) = pk;
    }
    __syncthreads();

    // per-thread h2 epilogue constants: cols o0 = ot*8 + (lane&3)*2, ot 0..7
    uint32_t vb[8], bb[8];
    #pragma unroll
    for (int ot = 0; ot < 8; ++ot) {
        const int o0 = ot * 8 + (lane & 3) * 2;
        vb[ot] = pack_f16x2(sv[o0], sv[o0 + 1]);
        bb[ot] = pack_f16x2(sbi[o0], sbi[o0 + 1]);
    }
    const int lrow = lane & 15, lcol8 = (lane >> 4) * 8;
    const int dlo = (lane & 3) * 2;   // within-16 k offset for B frags / xi pairs

    #pragma unroll
    for (int h = 0; h < 2; ++h) {
        // W fragments (B operand) for this o-half — loop-invariant over jt, il
        uint32_t Wb[4][4][2];
        #pragma unroll
        for (int ot4 = 0; ot4 < 4; ++ot4) {
            const int o = (h * 4 + ot4) * 8 + (lane >> 2);
            const float* Wr = sW + o * 65;
            #pragma unroll
            for (int kt = 0; kt < 4; ++kt) {
                const int d0 = kt * 16 + dlo;
                Wb[ot4][kt][0] = pack_f16x2(Wr[d0],     Wr[d0 + 1]);
                Wb[ot4][kt][1] = pack_f16x2(Wr[d0 + 8], Wr[d0 + 9]);
            }
        }

        for (int jt = 0; jt < 4; ++jt) {
            // raw Xj fragments for this j-tile — shared across all 8 i's
            uint32_t ar[4][4];
            #pragma unroll
            for (int kt = 0; kt < 4; ++kt) {
                uint32_t addr = sb32 + SM_XJ + (jt * 16 + lrow) * (XROW * 2) + (kt * 16 + lcol8) * 2;
                ldmatrix_x4(ar[kt][0], ar[kt][1], ar[kt][2], ar[kt][3], addr);
            }

            #pragma unroll
            for (int il = 0; il < 8; ++il) {
                const int i = w * 8 + il;
                // xi pairs (broadcast loads, f16x2)
                uint32_t xlo[4], xhi[4];
                #pragma unroll
                for (int kt = 0; kt < 4; ++kt) {
                    const uint32_t xa = sb32 + SM_XIH + i * (XROW * 2) + (kt * 16 + dlo) * 2;
                    asm volatile("ld.shared.b32 %0, [%1];" : "=r"(xlo[kt]) : "r"(xa));
                    asm volatile("ld.shared.b32 %0, [%1];" : "=r"(xhi[kt]) : "r"(xa + 16));
                }

                uint32_t c[4][2];
                #pragma unroll
                for (int ot4 = 0; ot4 < 4; ++ot4) { c[ot4][0] = 0u; c[ot4][1] = 0u; }

                #pragma unroll
                for (int kt = 0; kt < 4; ++kt) {
                    const uint32_t a0 = hmul2u(ar[kt][0], xlo[kt]);
                    const uint32_t a1 = hmul2u(ar[kt][1], xlo[kt]);
                    const uint32_t a2 = hmul2u(ar[kt][2], xhi[kt]);
                    const uint32_t a3 = hmul2u(ar[kt][3], xhi[kt]);
                    #pragma unroll
                    for (int ot4 = 0; ot4 < 4; ++ot4)
                        mma16816_h(c[ot4][0], c[ot4][1], a0, a1, a2, a3,
                                   Wb[ot4][kt][0], Wb[ot4][kt][1]);
                }

                // h2 epilogue: q = v ⊙ tanh(c + b); pairwise f16, then f32
                uint32_t q0[4], q1[4];
                #pragma unroll
                for (int ot4 = 0; ot4 < 4; ++ot4) {
                    const int e = h * 4 + ot4;
                    q0[ot4] = hmul2u(tanh_h2(hadd2u(c[ot4][0], bb[e])), vb[e]);
                    q1[ot4] = hmul2u(tanh_h2(hadd2u(c[ot4][1], bb[e])), vb[e]);
                }
                const uint32_t q001 = hadd2u(q0[0], q0[1]), q023 = hadd2u(q0[2], q0[3]);
                const uint32_t q101 = hadd2u(q1[0], q1[1]), q123 = hadd2u(q1[2], q1[3]);
                float2 f00 = h2f2(q001), f02 = h2f2(q023);
                float2 f10 = h2f2(q101), f12 = h2f2(q123);
                float s0 = (f00.x + f00.y) + (f02.x + f02.y);
                float s1 = (f10.x + f10.y) + (f12.x + f12.y);
                s0 += __shfl_xor_sync(0xffffffffu, s0, 1);
                s0 += __shfl_xor_sync(0xffffffffu, s0, 2);
                s1 += __shfl_xor_sync(0xffffffffu, s1, 1);
                s1 += __shfl_xor_sync(0xffffffffu, s1, 2);
                if ((lane & 3) == 0) {
                    float* d0 = sS + i * 65 + jt * 16 + (lane >> 2);
                    if (h == 0) { d0[0] = s0; d0[8] = s1; }
                    else        { d0[0] += s0; d0[8] += s1; }
                }
            }
        }
        __syncthreads();   // h=0 stores fully visible before h=1 RMW (same thread anyway) & before final writeout
    }

    {
        const int r = tid >> 2, cg = tid & 3;
        float* dst = g_scores + ((size_t)(b * 512 + ti * 64 + r)) * 512 + tj * 64 + cg * 16;
        #pragma unroll
        for (int q = 0; q < 4; ++q) {
            float4 vv = make_float4(sS[r * 65 + cg * 16 + q * 4 + 0],
                                    sS[r * 65 + cg * 16 + q * 4 + 1],
                                    sS[r * 65 + cg * 16 + q * 4 + 2],
                                    sS[r * 65 + cg * 16 + q * 4 + 3]);
            reinterpret_cast<float4*>(dst)[q] = vv;
        }
    }
    if (ti != tj) {
        const int jr = tid >> 2, cg = tid & 3;
        float* dst = g_scores + ((size_t)(b * 512 + tj * 64 + jr)) * 512 + ti * 64 + cg * 16;
        #pragma unroll
        for (int q = 0; q < 4; ++q) {
            float4 vv = make_float4(sS[(cg * 16 + q * 4 + 0) * 65 + jr],
                                    sS[(cg * 16 + q * 4 + 1) * 65 + jr],
                                    sS[(cg * 16 + q * 4 + 2) * 65 + jr],
                                    sS[(cg * 16 + q * 4 + 3) * 65 + jr]);
            reinterpret_cast<float4*>(dst)[q] = vv;
        }
    }
}

// ---------------- fused softmax+agg+proj kernel smem layout ------------------
#define EROW 520                      // bf16 elems per padded E row (1040 B)
#define SM_TX   0                     // 512*144 = 73728
#define SM_TE   73728                 // 64*1040 = 66560  (reused as sAgg after MMA)
#define SM_TINV 140288                // 256
#define SM_WW   140544                // 64*65*4 = 16640
#define SM_WO   157184                // 16640
#define SM_XF   173824                // 64*64*4 = 16384 (x fp32 rows)
#define SM_RS   190208                // 1024
#define SM_RQ   191232                // 1024
#define SMEM_T  192256

// ---------------------------------------------------------------------------
// Fused: softmax -> agg (MMA, trans-ldmatrix B) -> projections -> BN partials.
// CTA = (b, 64 i's). grid (8, 16), block 256.
// ---------------------------------------------------------------------------
__global__ void __launch_bounds__(256, 1)
smagg_kernel(const float* __restrict__ x,
             const float* __restrict__ Wwith, const float* __restrict__ bwith,
             const float* __restrict__ Wwo,   const float* __restrict__ bwo)
{
    extern __shared__ char smem[];
    const uint32_t sb32 = smem_u32(smem);
    const int tid = threadIdx.x, w = tid >> 5, lane = tid & 31;
    const int b = blockIdx.y, ibase = blockIdx.x * 64;
    const float* __restrict__ xb = x + (size_t)b * NN * DD;
    float* sinv = (float*)(smem + SM_TINV);
    float* sWw  = (float*)(smem + SM_WW);
    float* sWo  = (float*)(smem + SM_WO);
    float* sXf  = (float*)(smem + SM_XF);
    float* sAgg = (float*)(smem + SM_TE);     // valid after MMA phase
    float* rs   = (float*)(smem + SM_RS);
    float* rq   = (float*)(smem + SM_RQ);

    // ---- early loads: X bf16, weights, x fp32 rows ----
    for (int u = tid; u < 512 * 16; u += 256) {
        int r = u >> 4, q = u & 15;
        float4 v4 = *reinterpret_cast<const float4*>(xb + r * 64 + q * 4);
        uint2 pk = make_uint2(pack_bf16x2(v4.x, v4.y), pack_bf16x2(v4.z, v4.w));
        *reinterpret_cast<uint2*>(smem + SM_TX + r * (XROW * 2) + q * 8) = pk;
    }
    for (int idx = tid; idx < 64 * 64; idx += 256) {
        int o = idx >> 6, d = idx & 63;
        sWw[o * 65 + d] = Wwith[idx];
        sWo[o * 65 + d] = Wwo[idx];
    }
    for (int u = tid; u < 64 * 16; u += 256) {
        int r = u >> 4, q = u & 15;
        *reinterpret_cast<float4*>(sXf + r * 64 + q * 4) =
            *reinterpret_cast<const float4*>(xb + (ibase + r) * 64 + q * 4);
    }

    // ---- softmax: warp w handles rows il = w*8 + 0..7 ----
    for (int r = 0; r < 8; ++r) {
        const int il = w * 8 + r;
        const float* srow = g_scores + ((size_t)(b * 512 + ibase + il)) * 512;
        float v[16];
        #pragma unroll
        for (int q = 0; q < 16; ++q) v[q] = srow[lane + q * 32];
        float m = v[0];
        #pragma unroll
        for (int q = 1; q < 16; ++q) m = fmaxf(m, v[q]);
        #pragma unroll
        for (int o = 16; o; o >>= 1) m = fmaxf(m, __shfl_xor_sync(0xffffffffu, m, o));
        float sum = 0.0f;
        #pragma unroll
        for (int q = 0; q < 16; ++q) { v[q] = __expf(v[q] - m); sum += v[q]; }
        #pragma unroll
        for (int o = 16; o; o >>= 1) sum += __shfl_xor_sync(0xffffffffu, sum, o);
        #pragma unroll
        for (int q = 0; q < 16; ++q) {
            *reinterpret_cast<__nv_bfloat16*>(smem + SM_TE + il * (EROW * 2) + (lane + q * 32) * 2) =
                __float2bfloat16(v[q]);
        }
        if (lane == 0) sinv[il] = 1.0f / sum;
    }
    __syncthreads();

    // ---- agg MMA: warp w -> mt = w>>1 (16 i's), ntg = w&1 (32 d) ----
    const int mt = w >> 1, ntg = w & 1;
    const int i0 = mt * 16;
    float c[4][4];
    #pragma unroll
    for (int q = 0; q < 4; ++q) { c[q][0] = c[q][1] = c[q][2] = c[q][3] = 0.0f; }

    const int lrow = lane & 15, lcol8 = (lane >> 4) * 8;
    for (int kt = 0; kt < 32; ++kt) {
        const int k0 = kt * 16;
        uint32_t a0, a1, a2, a3;
        {
            uint32_t addr = sb32 + SM_TE + (i0 + lrow) * (EROW * 2) + (k0 + lcol8) * 2;
            ldmatrix_x4(a0, a1, a2, a3, addr);
        }
        // B fragments via trans-ldmatrix on X[j][d] (k=j rows, n=d cols)
        uint32_t bf[8];
        #pragma unroll
        for (int g = 0; g < 2; ++g) {
            const int n0 = ntg * 32 + g * 16;
            uint32_t addr = sb32 + SM_TX + (k0 + lrow) * (XROW * 2) + (n0 + lcol8) * 2;
            ldmatrix_x4_trans(bf[g * 4 + 0], bf[g * 4 + 1], bf[g * 4 + 2], bf[g * 4 + 3], addr);
        }
        #pragma unroll
        for (int q = 0; q < 4; ++q)
            mma16816(c[q][0], c[q][1], c[q][2], c[q][3], a0, a1, a2, a3,
                     bf[q * 2], bf[q * 2 + 1]);
    }
    __syncthreads();   // E no longer needed; TE region becomes sAgg

    // ---- write normalized agg into smem ----
    {
        const int r0 = i0 + (lane >> 2), r1 = r0 + 8;
        const float inv0 = sinv[r0], inv1 = sinv[r1];
        #pragma unroll
        for (int q = 0; q < 4; ++q) {
            const int d0 = ntg * 32 + q * 8 + (lane & 3) * 2;
            sAgg[r0 * 64 + d0]     = c[q][0] * inv0;
            sAgg[r0 * 64 + d0 + 1] = c[q][1] * inv0;
            sAgg[r1 * 64 + d0]     = c[q][2] * inv1;
            sAgg[r1 * 64 + d0 + 1] = c[q][3] * inv1;
        }
    }
    __syncthreads();

    // ---- projections + BN partials (former stage2, 64 rows) ----
    {
        const int o = tid & 63, rg = tid >> 6;     // 4 groups x 16 rows
        const float bias = bwith[o] + bwo[o];
        float lsum = 0.0f, lsq = 0.0f;
        for (int rr = 0; rr < 16; ++rr) {
            const int r = rg * 16 + rr;
            float acc = bias;
            #pragma unroll 8
            for (int d = 0; d < 64; ++d)
                acc += sAgg[r * 64 + d] * sWw[o * 65 + d]
                     + sXf [r * 64 + d] * sWo[o * 65 + d];
            g_xout[(size_t)(b * 512 + ibase + r) * 64 + o] = acc;
            lsum += acc;
            lsq  = fmaf(acc, acc, lsq);
        }
        rs[rg * 64 + o] = lsum;
        rq[rg * 64 + o] = lsq;
    }
    __syncthreads();
    if (tid < 64) {
        float s = rs[tid] + rs[64 + tid] + rs[128 + tid] + rs[192 + tid];
        float q = rq[tid] + rq[64 + tid] + rq[128 + tid] + rq[192 + tid];
        const int cta = blockIdx.y * 8 + blockIdx.x;   // 0..127
        g_ps[cta * 64 + tid] = s;
        g_pq[cta * 64 + tid] = q;
    }
}

// ---------------------------------------------------------------------------
// Stage 3a: one block per channel; 128 partials each. grid 64 x 128 threads.
// ---------------------------------------------------------------------------
__global__ void __launch_bounds__(128)
stage3a_kernel()
{
    __shared__ float rs[128], rq[128];
    const int o = blockIdx.x, t = threadIdx.x;
    rs[t] = g_ps[t * 64 + o];
    rq[t] = g_pq[t * 64 + o];
    __syncthreads();
    if (t < 32) {
        float ss = rs[t] + rs[t + 32] + rs[t + 64] + rs[t + 96];
        float qq = rq[t] + rq[t + 32] + rq[t + 64] + rq[t + 96];
        #pragma unroll
        for (int off = 16; off; off >>= 1) {
            ss += __shfl_xor_sync(0xffffffffu, ss, off);
            qq += __shfl_xor_sync(0xffffffffu, qq, off);
        }
        if (t == 0) {
            const float mean = ss * (1.0f / 8192.0f);
            const float var  = qq * (1.0f / 8192.0f) - mean * mean;
            g_mean[o] = mean;
            g_istd[o] = rsqrtf(var + BN_EPS);
        }
    }
}

__global__ void __launch_bounds__(512)
stage3b_kernel(const float* __restrict__ gamma, const float* __restrict__ beta,
               float* __restrict__ out)
{
    const int idx = blockIdx.x * 512 + threadIdx.x;
    const int o = idx & 63;
    float v = g_xout[idx];
    float n = (v - g_mean[o]) * g_istd[o] * gamma[o] + beta[o];
    const float alpha = 1.6732632423543772f;
    const float lam   = 1.0507009873554805f;
    out[idx] = (n > 0.0f) ? lam * n : lam * alpha * expm1f(n);
}

// ---------------------------------------------------------------------------
extern "C" void kernel_launch(void* const* d_in, const int* in_sizes, int n_in,
                              void* d_out, int out_size)
{
    const float* x     = (const float*)d_in[0];
    const float* Wap   = (const float*)d_in[1];
    const float* bap   = (const float*)d_in[2];
    const float* attw  = (const float*)d_in[3];
    const float* Wwith = (const float*)d_in[4];
    const float* bwith = (const float*)d_in[5];
    const float* Wwo   = (const float*)d_in[6];
    const float* bwo   = (const float*)d_in[7];
    const float* gamma = (const float*)d_in[8];
    const float* beta  = (const float*)d_in[9];
    float* out = (float*)d_out;

    cudaFuncSetAttribute(score_kernel,
                         cudaFuncAttributeMaxDynamicSharedMemorySize, SMEM_S);
    cudaFuncSetAttribute(smagg_kernel,
                         cudaFuncAttributeMaxDynamicSharedMemorySize, SMEM_T);

    dim3 gs(36, 16);
    score_kernel<<<gs, 256, SMEM_S>>>(x, Wap, bap, attw);
    dim3 gt(8, 16);
    smagg_kernel<<<gt, 256, SMEM_T>>>(x, Wwith, bwith, Wwo, bwo);
    stage3a_kernel<<<64, 128>>>();
    stage3b_kernel<<<(BB * NN * DD) / 512, 512>>>(gamma, beta, out);
}